// round 1
// baseline (speedup 1.0000x reference)
#include <cuda_runtime.h>
#include <math.h>

#define NN 100000
#define EPS 1e-5f

// ---------------- scratch (static device globals; no runtime allocation) ----
__device__ float g_norm[NN];
__device__ float g_agg1[NN * 128];
__device__ float g_z1[NN * 256];
__device__ float g_agg2[NN * 256];
__device__ float g_z2[NN * 256];
__device__ float g_xp[NN * 40];
__device__ float g_agg3[NN * 40];
__device__ double g_sum1[256], g_sq1[256], g_sum2[256], g_sq2[256];
__device__ float g_scale1[256], g_shift1[256], g_scale2[256], g_shift2[256];

// ---------------- helpers ----------------------------------------------------
__device__ __forceinline__ void red_add_v4(float* p, float4 v) {
    asm volatile("red.global.add.v4.f32 [%0], {%1,%2,%3,%4};"
                 :: "l"(p), "f"(v.x), "f"(v.y), "f"(v.z), "f"(v.w)
                 : "memory");
}

// ---------------- degree / norm ----------------------------------------------
__global__ void k_count_deg(const int* __restrict__ dst, int E) {
    int i = blockIdx.x * blockDim.x + threadIdx.x;
    if (i < E) atomicAdd(&g_norm[__ldg(dst + i)], 1.0f);
}

__global__ void k_norm_fin() {
    int i = blockIdx.x * blockDim.x + threadIdx.x;
    if (i < NN) g_norm[i] = rsqrtf(fmaxf(g_norm[i], 1.0f));
}

// ---------------- edge scatters ----------------------------------------------
// layer1: agg1[dst] += x[src] * norm[src]   (128 feats = 32 float4)
__global__ void k_scatter1(const int* __restrict__ src, const int* __restrict__ dst,
                           const float* __restrict__ x, int E) {
    int t = blockIdx.x * blockDim.x + threadIdx.x;
    if (t >= E * 32) return;
    int e = t >> 5, j = t & 31;
    int s = __ldg(src + e), d = __ldg(dst + e);
    float ns = g_norm[s];
    float4 v = __ldg((const float4*)x + (size_t)s * 32 + j);
    v.x *= ns; v.y *= ns; v.z *= ns; v.w *= ns;
    red_add_v4(g_agg1 + ((size_t)d * 32 + j) * 4, v);
}

// layer2: agg2[dst] += relu(bn(z1[src])) * norm[src]   (256 feats = 64 float4)
__global__ void k_scatter2(const int* __restrict__ src, const int* __restrict__ dst, int E) {
    int t = blockIdx.x * blockDim.x + threadIdx.x;
    if (t >= E * 64) return;
    int e = t >> 6, j = t & 63;
    int s = __ldg(src + e), d = __ldg(dst + e);
    float ns = g_norm[s];
    float4 z  = __ldg((const float4*)g_z1 + (size_t)s * 64 + j);
    float4 sc = __ldg((const float4*)g_scale1 + j);
    float4 sh = __ldg((const float4*)g_shift1 + j);
    float4 v;
    v.x = fmaxf(fmaf(z.x, sc.x, sh.x), 0.f) * ns;
    v.y = fmaxf(fmaf(z.y, sc.y, sh.y), 0.f) * ns;
    v.z = fmaxf(fmaf(z.z, sc.z, sh.z), 0.f) * ns;
    v.w = fmaxf(fmaf(z.w, sc.w, sh.w), 0.f) * ns;
    red_add_v4(g_agg2 + ((size_t)d * 64 + j) * 4, v);
}

// layer3: agg3[dst] += xp[src] * norm[src]   (40 feats = 10 float4)
__global__ void k_scatter3(const int* __restrict__ src, const int* __restrict__ dst, int E) {
    int t = blockIdx.x * blockDim.x + threadIdx.x;
    if (t >= E * 10) return;
    int e = t / 10, j = t % 10;
    int s = __ldg(src + e), d = __ldg(dst + e);
    float ns = g_norm[s];
    float4 v = __ldg((const float4*)g_xp + (size_t)s * 10 + j);
    v.x *= ns; v.y *= ns; v.z *= ns; v.w *= ns;
    red_add_v4(g_agg3 + ((size_t)d * 10 + j) * 4, v);
}

// ---------------- GEMM: C[M,N] = transform(A[M,K]) @ W[K,N] (+ bias) ---------
// MODE 0: a *= rowscale[m]; bias added       (graph-conv project-after)
// MODE 1: a = relu(a*cscale[k]+cshift[k]); no bias   (layer-3 project-first)
template <int MODE>
__global__ void k_gemm64(const float* __restrict__ A, const float* __restrict__ W,
                         const float* __restrict__ bias, float* __restrict__ C,
                         const float* __restrict__ rs,
                         const float* __restrict__ csc, const float* __restrict__ csh,
                         int M, int N, int K) {
    __shared__ float As[16][65];
    __shared__ float Bs[16][64];
    int tid = threadIdx.x;
    int tx = tid & 15, ty = tid >> 4;
    int m0 = blockIdx.x * 64, n0 = blockIdx.y * 64;
    float acc[4][4] = {};

    for (int k0 = 0; k0 < K; k0 += 16) {
        #pragma unroll
        for (int i = 0; i < 4; i++) {
            int idx = tid + i * 256;
            int r = idx >> 4, c = idx & 15;
            int m = m0 + r, k = k0 + c;
            float a = 0.f;
            if (m < M) {
                a = A[(size_t)m * K + k];
                if (MODE == 0) a *= rs[m];
                else           a = fmaxf(fmaf(a, csc[k], csh[k]), 0.f);
            }
            As[c][r] = a;
        }
        #pragma unroll
        for (int i = 0; i < 4; i++) {
            int idx = tid + i * 256;
            int kk = idx >> 6, n = idx & 63;
            float b = 0.f;
            if (n0 + n < N) b = W[(size_t)(k0 + kk) * N + (n0 + n)];
            Bs[kk][n] = b;
        }
        __syncthreads();
        #pragma unroll
        for (int k = 0; k < 16; k++) {
            float a[4], b[4];
            #pragma unroll
            for (int i = 0; i < 4; i++) a[i] = As[k][ty + 16 * i];
            #pragma unroll
            for (int j = 0; j < 4; j++) b[j] = Bs[k][tx + 16 * j];
            #pragma unroll
            for (int i = 0; i < 4; i++)
                #pragma unroll
                for (int j = 0; j < 4; j++) acc[i][j] = fmaf(a[i], b[j], acc[i][j]);
        }
        __syncthreads();
    }

    #pragma unroll
    for (int i = 0; i < 4; i++) {
        int m = m0 + ty + 16 * i;
        if (m >= M) continue;
        #pragma unroll
        for (int j = 0; j < 4; j++) {
            int n = n0 + tx + 16 * j;
            if (n < N) {
                float bb = (MODE == 0) ? bias[n] : 0.f;
                C[(size_t)m * N + n] = acc[i][j] + bb;
            }
        }
    }
}

// ---------------- BN column stats (coalesced, double accumulate) -------------
__global__ void k_colstats(const float* __restrict__ Z, double* __restrict__ sum,
                           double* __restrict__ sq, int M) {
    int col = threadIdx.x;  // 256 threads = 256 columns
    int r0 = blockIdx.x * 512;
    int rend = min(r0 + 512, M);
    float s = 0.f, q = 0.f;
    for (int r = r0; r < rend; r++) {
        float v = Z[(size_t)r * 256 + col];
        s += v;
        q = fmaf(v, v, q);
    }
    atomicAdd(&sum[col], (double)s);
    atomicAdd(&sq[col],  (double)q);
}

__global__ void k_bnfin(const double* __restrict__ sum, const double* __restrict__ sq,
                        const float* __restrict__ gamma, const float* __restrict__ beta,
                        float* __restrict__ scale, float* __restrict__ shift) {
    int i = threadIdx.x;
    double mean = sum[i] / (double)NN;
    double var  = sq[i] / (double)NN - mean * mean;
    float rstd = (float)(1.0 / sqrt(var + (double)EPS));
    float sc = rstd * gamma[i];
    scale[i] = sc;
    shift[i] = beta[i] - (float)mean * sc;
}

// ---------------- final: out = log_softmax(agg3*norm + b3) -------------------
__global__ void k_final(const float* __restrict__ b3, float* __restrict__ out) {
    int gt = blockIdx.x * blockDim.x + threadIdx.x;
    int node = gt >> 5;
    int lane = gt & 31;
    if (node >= NN) return;
    float nrm = g_norm[node];
    float v0 = g_agg3[(size_t)node * 40 + lane] * nrm + __ldg(b3 + lane);
    float v1 = -1e30f;
    if (lane + 32 < 40)
        v1 = g_agg3[(size_t)node * 40 + lane + 32] * nrm + __ldg(b3 + lane + 32);
    float m = fmaxf(v0, v1);
    #pragma unroll
    for (int o = 16; o; o >>= 1) m = fmaxf(m, __shfl_xor_sync(0xffffffffu, m, o));
    float s = expf(v0 - m) + ((lane + 32 < 40) ? expf(v1 - m) : 0.f);
    #pragma unroll
    for (int o = 16; o; o >>= 1) s += __shfl_xor_sync(0xffffffffu, s, o);
    float ls = logf(s);
    out[(size_t)node * 40 + lane] = v0 - m - ls;
    if (lane + 32 < 40)
        out[(size_t)node * 40 + lane + 32] = v1 - m - ls;
}

// ---------------- launch -----------------------------------------------------
extern "C" void kernel_launch(void* const* d_in, const int* in_sizes, int n_in,
                              void* d_out, int out_size) {
    const float* x      = (const float*)d_in[0];
    const int*   src    = (const int*)  d_in[1];
    const int*   dst    = (const int*)  d_in[2];
    const float* W1     = (const float*)d_in[3];
    const float* b1     = (const float*)d_in[4];
    const float* gamma1 = (const float*)d_in[5];
    const float* beta1  = (const float*)d_in[6];
    const float* W2     = (const float*)d_in[7];
    const float* b2     = (const float*)d_in[8];
    const float* gamma2 = (const float*)d_in[9];
    const float* beta2  = (const float*)d_in[10];
    const float* W3     = (const float*)d_in[11];
    const float* b3     = (const float*)d_in[12];
    float* out = (float*)d_out;
    int E = in_sizes[1];

    void *p_norm, *p_agg1, *p_z1, *p_agg2, *p_z2, *p_xp, *p_agg3;
    void *p_sum1, *p_sq1, *p_sum2, *p_sq2, *p_sc1, *p_sh1, *p_sc2, *p_sh2;
    cudaGetSymbolAddress(&p_norm, g_norm);
    cudaGetSymbolAddress(&p_agg1, g_agg1);
    cudaGetSymbolAddress(&p_z1,   g_z1);
    cudaGetSymbolAddress(&p_agg2, g_agg2);
    cudaGetSymbolAddress(&p_z2,   g_z2);
    cudaGetSymbolAddress(&p_xp,   g_xp);
    cudaGetSymbolAddress(&p_agg3, g_agg3);
    cudaGetSymbolAddress(&p_sum1, g_sum1);
    cudaGetSymbolAddress(&p_sq1,  g_sq1);
    cudaGetSymbolAddress(&p_sum2, g_sum2);
    cudaGetSymbolAddress(&p_sq2,  g_sq2);
    cudaGetSymbolAddress(&p_sc1,  g_scale1);
    cudaGetSymbolAddress(&p_sh1,  g_shift1);
    cudaGetSymbolAddress(&p_sc2,  g_scale2);
    cudaGetSymbolAddress(&p_sh2,  g_shift2);

    cudaMemsetAsync(p_norm, 0, NN * sizeof(float), 0);
    cudaMemsetAsync(p_agg1, 0, (size_t)NN * 128 * sizeof(float), 0);
    cudaMemsetAsync(p_agg2, 0, (size_t)NN * 256 * sizeof(float), 0);
    cudaMemsetAsync(p_agg3, 0, (size_t)NN * 40 * sizeof(float), 0);
    cudaMemsetAsync(p_sum1, 0, 256 * sizeof(double), 0);
    cudaMemsetAsync(p_sq1,  0, 256 * sizeof(double), 0);
    cudaMemsetAsync(p_sum2, 0, 256 * sizeof(double), 0);
    cudaMemsetAsync(p_sq2,  0, 256 * sizeof(double), 0);

    const int T = 256;
    int mg = (NN + 63) / 64;  // 1563

    // degree / norm
    k_count_deg<<<(E + T - 1) / T, T>>>(dst, E);
    k_norm_fin<<<(NN + T - 1) / T, T>>>();

    // layer 1: scatter(x*norm) -> gemm(*norm, +b1) -> BN stats
    k_scatter1<<<((long long)E * 32 + T - 1) / T, T>>>(src, dst, x, E);
    k_gemm64<0><<<dim3(mg, 4), T>>>((const float*)p_agg1, W1, b1, (float*)p_z1,
                                    (const float*)p_norm, nullptr, nullptr,
                                    NN, 256, 128);
    k_colstats<<<(NN + 511) / 512, 256>>>((const float*)p_z1, (double*)p_sum1,
                                          (double*)p_sq1, NN);
    k_bnfin<<<1, 256>>>((const double*)p_sum1, (const double*)p_sq1, gamma1, beta1,
                        (float*)p_sc1, (float*)p_sh1);

    // layer 2: scatter(relu(bn(z1))*norm) -> gemm(*norm, +b2) -> BN stats
    k_scatter2<<<((long long)E * 64 + T - 1) / T, T>>>(src, dst, E);
    k_gemm64<0><<<dim3(mg, 4), T>>>((const float*)p_agg2, W2, b2, (float*)p_z2,
                                    (const float*)p_norm, nullptr, nullptr,
                                    NN, 256, 256);
    k_colstats<<<(NN + 511) / 512, 256>>>((const float*)p_z2, (double*)p_sum2,
                                          (double*)p_sq2, NN);
    k_bnfin<<<1, 256>>>((const double*)p_sum2, (const double*)p_sq2, gamma2, beta2,
                        (float*)p_sc2, (float*)p_sh2);

    // layer 3: project-first gemm(relu(bn(z2)) @ W3) -> scatter -> log_softmax
    k_gemm64<1><<<dim3(mg, 1), T>>>((const float*)p_z2, W3, nullptr, (float*)p_xp,
                                    nullptr, (const float*)p_sc2, (const float*)p_sh2,
                                    NN, 40, 256);
    k_scatter3<<<((long long)E * 10 + T - 1) / T, T>>>(src, dst, E);
    k_final<<<((long long)NN * 32 + T - 1) / T, T>>>(b3, out);
}

// round 2
// speedup vs baseline: 2.1083x; 2.1083x over previous
#include <cuda_runtime.h>
#include <cuda_fp16.h>
#include <math.h>

#define NN 100000
#define EPS 1e-5f

// ---------------- scratch (static device globals) ----------------------------
__device__ int    g_deg[NN];
__device__ int    g_off[NN + 1];
__device__ int    g_cur[NN];
__device__ int    g_csr[3200000];
__device__ float  g_norm[NN];
__device__ __half g_h0[NN * 128];        // x * norm[src], half
__device__ float  g_agg1[NN * 128];
__device__ float  g_z1[NN * 256];
__device__ __half g_h1[NN * 256];        // relu(bn(z1)) * norm[src], half
__device__ float  g_agg2[NN * 256];
__device__ float  g_z2[NN * 256];
__device__ float  g_xp[NN * 40];
__device__ float  g_agg3[NN * 40];
__device__ double g_stats[4 * 256];      // sum1, sq1, sum2, sq2
__device__ float  g_bnp[4 * 256];        // scale1, shift1, scale2, shift2

// ---------------- f32x2 packed-FMA helpers -----------------------------------
__device__ __forceinline__ unsigned long long pk2(float lo, float hi) {
    unsigned long long r;
    asm("mov.b64 %0, {%1,%2};" : "=l"(r) : "f"(lo), "f"(hi));
    return r;
}
__device__ __forceinline__ void fma2(unsigned long long& d, unsigned long long a,
                                     unsigned long long b) {
    asm("fma.rn.f32x2 %0, %1, %2, %3;" : "=l"(d) : "l"(a), "l"(b), "l"(d));
}
__device__ __forceinline__ float2 up2(unsigned long long v) {
    float2 f;
    asm("mov.b64 {%0,%1}, %2;" : "=f"(f.x), "=f"(f.y) : "l"(v));
    return f;
}

// ---------------- CSR build ---------------------------------------------------
__global__ void k_hist(const int* __restrict__ dst, int E) {
    int i = blockIdx.x * blockDim.x + threadIdx.x;
    if (i < E) atomicAdd(&g_deg[__ldg(dst + i)], 1);
}

__global__ void k_scan() {
    __shared__ int sh[1024];
    int tid = threadIdx.x;
    const int C = (NN + 1023) / 1024;
    int base = tid * C;
    int s = 0;
    for (int i = 0; i < C; i++) {
        int idx = base + i;
        if (idx < NN) s += g_deg[idx];
    }
    sh[tid] = s;
    __syncthreads();
    for (int o = 1; o < 1024; o <<= 1) {
        int v = (tid >= o) ? sh[tid - o] : 0;
        __syncthreads();
        sh[tid] += v;
        __syncthreads();
    }
    int run = tid ? sh[tid - 1] : 0;
    for (int i = 0; i < C; i++) {
        int idx = base + i;
        if (idx < NN) {
            g_off[idx] = run;
            g_cur[idx] = run;
            run += g_deg[idx];
        }
    }
    if (tid == 1023) g_off[NN] = sh[1023];
}

__global__ void k_fill(const int* __restrict__ src, const int* __restrict__ dst, int E) {
    int i = blockIdx.x * blockDim.x + threadIdx.x;
    if (i < E) {
        int d = __ldg(dst + i);
        int p = atomicAdd(&g_cur[d], 1);
        g_csr[p] = __ldg(src + i);
    }
}

__global__ void k_norm_fin() {
    int i = blockIdx.x * blockDim.x + threadIdx.x;
    if (i < NN) g_norm[i] = rsqrtf(fmaxf((float)g_deg[i], 1.0f));
}

// ---------------- feature prep (fp32 -> premultiplied half) ------------------
__global__ void k_prep0(const float* __restrict__ x) {
    int t = blockIdx.x * blockDim.x + threadIdx.x;
    if (t >= NN * 64) return;
    int row = t >> 6;
    float n = g_norm[row];
    float2 v = __ldg((const float2*)x + t);
    ((__half2*)g_h0)[t] = __floats2half2_rn(v.x * n, v.y * n);
}

__global__ void k_prep1() {
    int t = blockIdx.x * blockDim.x + threadIdx.x;
    if (t >= NN * 128) return;
    int row = t >> 7, c2 = t & 127;
    float n = g_norm[row];
    float2 z  = ((const float2*)g_z1)[t];
    float2 sc = ((const float2*)g_bnp)[c2];
    float2 sh = ((const float2*)(g_bnp + 256))[c2];
    float a = fmaxf(fmaf(z.x, sc.x, sh.x), 0.f) * n;
    float b = fmaxf(fmaf(z.y, sc.y, sh.y), 0.f) * n;
    ((__half2*)g_h1)[t] = __floats2half2_rn(a, b);
}

// ---------------- CSR gathers (no atomics) ------------------------------------
template <int FEAT>
__global__ void k_gather_h(const __half* __restrict__ H, float* __restrict__ AGG) {
    const int G = FEAT / 8;  // threads per node, each owns 8 halfs (16B)
    int node = blockIdx.x * (256 / G) + threadIdx.x / G;
    int t = threadIdx.x % G;
    if (node >= NN) return;
    int beg = g_off[node], end = g_off[node + 1];
    const uint4* Hv = reinterpret_cast<const uint4*>(H);
    float acc[8] = {0, 0, 0, 0, 0, 0, 0, 0};
    for (int j = beg; j < end; j++) {
        int s = __ldg(g_csr + j);
        uint4 u = __ldg(Hv + (size_t)s * G + t);
        float2 f0 = __half22float2(*reinterpret_cast<__half2*>(&u.x));
        float2 f1 = __half22float2(*reinterpret_cast<__half2*>(&u.y));
        float2 f2 = __half22float2(*reinterpret_cast<__half2*>(&u.z));
        float2 f3 = __half22float2(*reinterpret_cast<__half2*>(&u.w));
        acc[0] += f0.x; acc[1] += f0.y; acc[2] += f1.x; acc[3] += f1.y;
        acc[4] += f2.x; acc[5] += f2.y; acc[6] += f3.x; acc[7] += f3.y;
    }
    float nd = g_norm[node];
    float* o = AGG + (size_t)node * FEAT + t * 8;
    float4 o0 = {acc[0] * nd, acc[1] * nd, acc[2] * nd, acc[3] * nd};
    float4 o1 = {acc[4] * nd, acc[5] * nd, acc[6] * nd, acc[7] * nd};
    *(float4*)o = o0;
    *(float4*)(o + 4) = o1;
}

// layer3: agg3[n] = sum_{s in N(n)} xp[s] * norm[s]   (fp32, 40 feats)
__global__ void k_gather3() {
    int node = blockIdx.x * 16 + threadIdx.x / 16;
    int t = threadIdx.x % 16;
    if (node >= NN || t >= 10) return;
    int beg = g_off[node], end = g_off[node + 1];
    float4 acc = {0, 0, 0, 0};
    for (int j = beg; j < end; j++) {
        int s = __ldg(g_csr + j);
        float ns = g_norm[s];
        float4 v = __ldg((const float4*)g_xp + (size_t)s * 10 + t);
        acc.x = fmaf(v.x, ns, acc.x);
        acc.y = fmaf(v.y, ns, acc.y);
        acc.z = fmaf(v.z, ns, acc.z);
        acc.w = fmaf(v.w, ns, acc.w);
    }
    ((float4*)g_agg3)[(size_t)node * 10 + t] = acc;
}

// ---------------- GEMM: C[M,N] = transform(A[M,K]) @ W[K,N] (+ bias) ---------
// MODE 0: plain A, bias added.   MODE 1: A <- relu(A*csc[k]+csh[k]), no bias.
// 128x64 block tile, 256 threads, 8x4 per thread, double-buffered, f32x2 math.
template <int MODE>
__global__ void __launch_bounds__(256) k_gemm(
    const float* __restrict__ A, const float* __restrict__ W,
    const float* __restrict__ bias, float* __restrict__ C,
    const float* __restrict__ csc, const float* __restrict__ csh,
    int M, int N, int K) {
    __shared__ float As[2][128][17];
    __shared__ __align__(16) float Bs[2][16][64];
    int tid = threadIdx.x;
    int tx = tid & 15, ty = tid >> 4;
    int m0 = blockIdx.x * 128, n0 = blockIdx.y * 64;
    int nt = K / 16;

    unsigned long long acc[8][2];
    #pragma unroll
    for (int i = 0; i < 8; i++) { acc[i][0] = 0ull; acc[i][1] = 0ull; }

    float4 ar[2], br;

    // ---- prologue: load tile 0 ----
    #pragma unroll
    for (int i = 0; i < 2; i++) {
        int f = tid + i * 256, m = f >> 2, q = f & 3;
        int gm = m0 + m;
        float4 v = {0.f, 0.f, 0.f, 0.f};
        if (gm < M) v = *(const float4*)(A + (size_t)gm * K + q * 4);
        if (MODE == 1) {
            float4 sc = *(const float4*)(csc + q * 4);
            float4 sh = *(const float4*)(csh + q * 4);
            v.x = fmaxf(fmaf(v.x, sc.x, sh.x), 0.f);
            v.y = fmaxf(fmaf(v.y, sc.y, sh.y), 0.f);
            v.z = fmaxf(fmaf(v.z, sc.z, sh.z), 0.f);
            v.w = fmaxf(fmaf(v.w, sc.w, sh.w), 0.f);
        }
        ar[i] = v;
    }
    {
        int kk = tid >> 4, n4 = tid & 15;
        if (MODE == 0) {
            br = *(const float4*)(W + (size_t)kk * N + n0 + n4 * 4);
        } else {
            int nb = n0 + n4 * 4;
            br.x = (nb + 0 < N) ? W[(size_t)kk * N + nb + 0] : 0.f;
            br.y = (nb + 1 < N) ? W[(size_t)kk * N + nb + 1] : 0.f;
            br.z = (nb + 2 < N) ? W[(size_t)kk * N + nb + 2] : 0.f;
            br.w = (nb + 3 < N) ? W[(size_t)kk * N + nb + 3] : 0.f;
        }
    }
    #pragma unroll
    for (int i = 0; i < 2; i++) {
        int f = tid + i * 256, m = f >> 2, q = f & 3;
        As[0][m][q * 4 + 0] = ar[i].x;
        As[0][m][q * 4 + 1] = ar[i].y;
        As[0][m][q * 4 + 2] = ar[i].z;
        As[0][m][q * 4 + 3] = ar[i].w;
    }
    {
        int kk = tid >> 4, n4 = tid & 15;
        *(float4*)&Bs[0][kk][n4 * 4] = br;
    }

    // ---- main loop ----
    for (int t = 0; t < nt; t++) {
        __syncthreads();
        if (t + 1 < nt) {
            int k0 = (t + 1) * 16;
            #pragma unroll
            for (int i = 0; i < 2; i++) {
                int f = tid + i * 256, m = f >> 2, q = f & 3;
                int gm = m0 + m;
                float4 v = {0.f, 0.f, 0.f, 0.f};
                if (gm < M) v = *(const float4*)(A + (size_t)gm * K + k0 + q * 4);
                if (MODE == 1) {
                    float4 sc = *(const float4*)(csc + k0 + q * 4);
                    float4 sh = *(const float4*)(csh + k0 + q * 4);
                    v.x = fmaxf(fmaf(v.x, sc.x, sh.x), 0.f);
                    v.y = fmaxf(fmaf(v.y, sc.y, sh.y), 0.f);
                    v.z = fmaxf(fmaf(v.z, sc.z, sh.z), 0.f);
                    v.w = fmaxf(fmaf(v.w, sc.w, sh.w), 0.f);
                }
                ar[i] = v;
            }
            int kk = tid >> 4, n4 = tid & 15;
            if (MODE == 0) {
                br = *(const float4*)(W + (size_t)(k0 + kk) * N + n0 + n4 * 4);
            } else {
                int nb = n0 + n4 * 4;
                br.x = (nb + 0 < N) ? W[(size_t)(k0 + kk) * N + nb + 0] : 0.f;
                br.y = (nb + 1 < N) ? W[(size_t)(k0 + kk) * N + nb + 1] : 0.f;
                br.z = (nb + 2 < N) ? W[(size_t)(k0 + kk) * N + nb + 2] : 0.f;
                br.w = (nb + 3 < N) ? W[(size_t)(k0 + kk) * N + nb + 3] : 0.f;
            }
        }
        int b = t & 1;
        #pragma unroll
        for (int k = 0; k < 16; k++) {
            unsigned long long a2[8];
            #pragma unroll
            for (int i = 0; i < 4; i++) {
                float alo = As[b][ty * 4 + i][k];
                float ahi = As[b][64 + ty * 4 + i][k];
                a2[i] = pk2(alo, alo);
                a2[4 + i] = pk2(ahi, ahi);
            }
            float4 bv = *(float4*)&Bs[b][k][tx * 4];
            unsigned long long b0 = pk2(bv.x, bv.y);
            unsigned long long b1 = pk2(bv.z, bv.w);
            #pragma unroll
            for (int i = 0; i < 8; i++) {
                fma2(acc[i][0], a2[i], b0);
                fma2(acc[i][1], a2[i], b1);
            }
        }
        if (t + 1 < nt) {
            int nb = (t + 1) & 1;
            #pragma unroll
            for (int i = 0; i < 2; i++) {
                int f = tid + i * 256, m = f >> 2, q = f & 3;
                As[nb][m][q * 4 + 0] = ar[i].x;
                As[nb][m][q * 4 + 1] = ar[i].y;
                As[nb][m][q * 4 + 2] = ar[i].z;
                As[nb][m][q * 4 + 3] = ar[i].w;
            }
            int kk = tid >> 4, n4 = tid & 15;
            *(float4*)&Bs[nb][kk][n4 * 4] = br;
        }
    }

    // ---- epilogue ----
    #pragma unroll
    for (int i = 0; i < 8; i++) {
        int m = m0 + ((i < 4) ? (ty * 4 + i) : (64 + ty * 4 + i - 4));
        if (m >= M) continue;
        float2 lo = up2(acc[i][0]);
        float2 hi = up2(acc[i][1]);
        int n = n0 + tx * 4;
        if (MODE == 0) {
            float4 o;
            o.x = lo.x + bias[n + 0];
            o.y = lo.y + bias[n + 1];
            o.z = hi.x + bias[n + 2];
            o.w = hi.y + bias[n + 3];
            *(float4*)(C + (size_t)m * N + n) = o;
        } else {
            if (n + 0 < N) C[(size_t)m * N + n + 0] = lo.x;
            if (n + 1 < N) C[(size_t)m * N + n + 1] = lo.y;
            if (n + 2 < N) C[(size_t)m * N + n + 2] = hi.x;
            if (n + 3 < N) C[(size_t)m * N + n + 3] = hi.y;
        }
    }
}

// ---------------- BN column stats (coalesced, double accumulate) -------------
__global__ void k_colstats(const float* __restrict__ Z, double* __restrict__ sum,
                           double* __restrict__ sq, int M) {
    int col = threadIdx.x;
    int r0 = blockIdx.x * 512;
    int rend = min(r0 + 512, M);
    float s = 0.f, q = 0.f;
    for (int r = r0; r < rend; r++) {
        float v = Z[(size_t)r * 256 + col];
        s += v;
        q = fmaf(v, v, q);
    }
    atomicAdd(&sum[col], (double)s);
    atomicAdd(&sq[col], (double)q);
}

__global__ void k_bnfin(const double* __restrict__ sum, const double* __restrict__ sq,
                        const float* __restrict__ gamma, const float* __restrict__ beta,
                        float* __restrict__ scale, float* __restrict__ shift) {
    int i = threadIdx.x;
    double mean = sum[i] / (double)NN;
    double var = sq[i] / (double)NN - mean * mean;
    float rstd = (float)(1.0 / sqrt(var + (double)EPS));
    float sc = rstd * gamma[i];
    scale[i] = sc;
    shift[i] = beta[i] - (float)mean * sc;
}

// ---------------- final: out = log_softmax(agg3*norm + b3) -------------------
__global__ void k_final(const float* __restrict__ b3, float* __restrict__ out) {
    int gt = blockIdx.x * blockDim.x + threadIdx.x;
    int node = gt >> 5;
    int lane = gt & 31;
    if (node >= NN) return;
    float nrm = g_norm[node];
    float v0 = g_agg3[(size_t)node * 40 + lane] * nrm + __ldg(b3 + lane);
    float v1 = -1e30f;
    if (lane + 32 < 40)
        v1 = g_agg3[(size_t)node * 40 + lane + 32] * nrm + __ldg(b3 + lane + 32);
    float m = fmaxf(v0, v1);
    #pragma unroll
    for (int o = 16; o; o >>= 1) m = fmaxf(m, __shfl_xor_sync(0xffffffffu, m, o));
    float s = expf(v0 - m) + ((lane + 32 < 40) ? expf(v1 - m) : 0.f);
    #pragma unroll
    for (int o = 16; o; o >>= 1) s += __shfl_xor_sync(0xffffffffu, s, o);
    float ls = logf(s);
    out[(size_t)node * 40 + lane] = v0 - m - ls;
    if (lane + 32 < 40)
        out[(size_t)node * 40 + lane + 32] = v1 - m - ls;
}

// ---------------- launch -----------------------------------------------------
extern "C" void kernel_launch(void* const* d_in, const int* in_sizes, int n_in,
                              void* d_out, int out_size) {
    const float* x      = (const float*)d_in[0];
    const int*   src    = (const int*)  d_in[1];
    const int*   dst    = (const int*)  d_in[2];
    const float* W1     = (const float*)d_in[3];
    const float* b1     = (const float*)d_in[4];
    const float* gamma1 = (const float*)d_in[5];
    const float* beta1  = (const float*)d_in[6];
    const float* W2     = (const float*)d_in[7];
    const float* b2     = (const float*)d_in[8];
    const float* gamma2 = (const float*)d_in[9];
    const float* beta2  = (const float*)d_in[10];
    const float* W3     = (const float*)d_in[11];
    const float* b3     = (const float*)d_in[12];
    float* out = (float*)d_out;
    int E = in_sizes[1];

    void *p_deg, *p_stats, *p_bnp, *p_h0, *p_h1;
    void *p_agg1, *p_z1, *p_agg2, *p_z2, *p_xp;
    cudaGetSymbolAddress(&p_deg,   g_deg);
    cudaGetSymbolAddress(&p_stats, g_stats);
    cudaGetSymbolAddress(&p_bnp,   g_bnp);
    cudaGetSymbolAddress(&p_h0,    g_h0);
    cudaGetSymbolAddress(&p_h1,    g_h1);
    cudaGetSymbolAddress(&p_agg1,  g_agg1);
    cudaGetSymbolAddress(&p_z1,    g_z1);
    cudaGetSymbolAddress(&p_agg2,  g_agg2);
    cudaGetSymbolAddress(&p_z2,    g_z2);
    cudaGetSymbolAddress(&p_xp,    g_xp);

    cudaMemsetAsync(p_deg, 0, NN * sizeof(int), 0);
    cudaMemsetAsync(p_stats, 0, 4 * 256 * sizeof(double), 0);

    const int T = 256;
    double* st = (double*)p_stats;
    float* bnp = (float*)p_bnp;

    // CSR build + norms
    k_hist<<<(E + T - 1) / T, T>>>(dst, E);
    k_scan<<<1, 1024>>>();
    k_fill<<<(E + T - 1) / T, T>>>(src, dst, E);
    k_norm_fin<<<(NN + T - 1) / T, T>>>();

    // layer 1
    k_prep0<<<(NN * 64 + T - 1) / T, T>>>(x);
    k_gather_h<128><<<(NN + 15) / 16, T>>>((const __half*)p_h0, (float*)p_agg1);
    k_gemm<0><<<dim3((NN + 127) / 128, 4), T>>>((const float*)p_agg1, W1, b1,
                                                (float*)p_z1, nullptr, nullptr,
                                                NN, 256, 128);
    k_colstats<<<(NN + 511) / 512, 256>>>((const float*)p_z1, st, st + 256, NN);
    k_bnfin<<<1, 256>>>(st, st + 256, gamma1, beta1, bnp, bnp + 256);

    // layer 2
    k_prep1<<<(NN * 128 + T - 1) / T, T>>>();
    k_gather_h<256><<<(NN + 7) / 8, T>>>((const __half*)p_h1, (float*)p_agg2);
    k_gemm<0><<<dim3((NN + 127) / 128, 4), T>>>((const float*)p_agg2, W2, b2,
                                                (float*)p_z2, nullptr, nullptr,
                                                NN, 256, 256);
    k_colstats<<<(NN + 511) / 512, 256>>>((const float*)p_z2, st + 512, st + 768, NN);
    k_bnfin<<<1, 256>>>(st + 512, st + 768, gamma2, beta2, bnp + 512, bnp + 768);

    // layer 3: project-first, then gather, then log_softmax
    k_gemm<1><<<dim3((NN + 127) / 128, 1), T>>>((const float*)p_z2, W3, nullptr,
                                                (float*)p_xp, bnp + 512, bnp + 768,
                                                NN, 40, 256);
    k_gather3<<<(NN + 15) / 16, T>>>();
    k_final<<<((long long)NN * 32 + T - 1) / T, T>>>(b3, out);
}

// round 3
// speedup vs baseline: 2.1188x; 1.0050x over previous
#include <cuda_runtime.h>
#include <cuda_fp16.h>
#include <math.h>

#define NN 100000
#define EPS 1e-5f

// ---------------- scratch (static device globals) ----------------------------
__device__ int    g_deg[NN];
__device__ int    g_off[NN + 1];
__device__ int    g_cur[NN];
__device__ int    g_csr[3200000];
__device__ float  g_norm[NN];
__device__ __half g_h0[NN * 128];        // x * norm[src], half
__device__ float  g_agg1[NN * 128];
__device__ float  g_z1[NN * 256];
__device__ __half g_h1[NN * 256];        // relu(bn(z1)) * norm[src], half
__device__ float  g_agg2[NN * 256];
__device__ float  g_z2[NN * 256];
__device__ float  g_xp[NN * 40];
__device__ float  g_agg3[NN * 40];
__device__ double g_stats[4 * 256];      // sum1, sq1, sum2, sq2
__device__ float  g_bnp[4 * 256];        // scale1, shift1, scale2, shift2

// ---------------- f32x2 packed-FMA helpers -----------------------------------
__device__ __forceinline__ unsigned long long pk2(float lo, float hi) {
    unsigned long long r;
    asm("mov.b64 %0, {%1,%2};" : "=l"(r) : "f"(lo), "f"(hi));
    return r;
}
__device__ __forceinline__ void fma2(unsigned long long& d, unsigned long long a,
                                     unsigned long long b) {
    asm("fma.rn.f32x2 %0, %1, %2, %3;" : "=l"(d) : "l"(a), "l"(b), "l"(d));
}
__device__ __forceinline__ float2 up2(unsigned long long v) {
    float2 f;
    asm("mov.b64 {%0,%1}, %2;" : "=f"(f.x), "=f"(f.y) : "l"(v));
    return f;
}

// ---------------- CSR build ---------------------------------------------------
__global__ void k_hist(const int* __restrict__ dst, int E) {
    int i = blockIdx.x * blockDim.x + threadIdx.x;
    if (i < E) atomicAdd(&g_deg[__ldg(dst + i)], 1);
}

__global__ void k_scan() {
    __shared__ int sh[1024];
    int tid = threadIdx.x;
    const int C = (NN + 1023) / 1024;
    int base = tid * C;
    int s = 0;
    for (int i = 0; i < C; i++) {
        int idx = base + i;
        if (idx < NN) s += g_deg[idx];
    }
    sh[tid] = s;
    __syncthreads();
    for (int o = 1; o < 1024; o <<= 1) {
        int v = (tid >= o) ? sh[tid - o] : 0;
        __syncthreads();
        sh[tid] += v;
        __syncthreads();
    }
    int run = tid ? sh[tid - 1] : 0;
    for (int i = 0; i < C; i++) {
        int idx = base + i;
        if (idx < NN) {
            g_off[idx] = run;
            g_cur[idx] = run;
            run += g_deg[idx];
        }
    }
    if (tid == 1023) g_off[NN] = sh[1023];
}

__global__ void k_fill(const int* __restrict__ src, const int* __restrict__ dst, int E) {
    int i = blockIdx.x * blockDim.x + threadIdx.x;
    if (i < E) {
        int d = __ldg(dst + i);
        int p = atomicAdd(&g_cur[d], 1);
        g_csr[p] = __ldg(src + i);
    }
}

__global__ void k_norm_fin() {
    int i = blockIdx.x * blockDim.x + threadIdx.x;
    if (i < NN) g_norm[i] = rsqrtf(fmaxf((float)g_deg[i], 1.0f));
}

// ---------------- feature prep (fp32 -> premultiplied half) ------------------
__global__ void k_prep0(const float* __restrict__ x) {
    int t = blockIdx.x * blockDim.x + threadIdx.x;
    if (t >= NN * 64) return;
    int row = t >> 6;
    float n = g_norm[row];
    float2 v = __ldg((const float2*)x + t);
    ((__half2*)g_h0)[t] = __floats2half2_rn(v.x * n, v.y * n);
}

__global__ void k_prep1() {
    int t = blockIdx.x * blockDim.x + threadIdx.x;
    if (t >= NN * 128) return;
    int row = t >> 7, c2 = t & 127;
    float n = g_norm[row];
    float2 z  = ((const float2*)g_z1)[t];
    float2 sc = ((const float2*)g_bnp)[c2];
    float2 sh = ((const float2*)(g_bnp + 256))[c2];
    float a = fmaxf(fmaf(z.x, sc.x, sh.x), 0.f) * n;
    float b = fmaxf(fmaf(z.y, sc.y, sh.y), 0.f) * n;
    ((__half2*)g_h1)[t] = __floats2half2_rn(a, b);
}

// ---------------- CSR gathers (no atomics) ------------------------------------
template <int FEAT>
__global__ void k_gather_h(const __half* __restrict__ H, float* __restrict__ AGG) {
    const int G = FEAT / 8;  // threads per node, each owns 8 halfs (16B)
    int node = blockIdx.x * (256 / G) + threadIdx.x / G;
    int t = threadIdx.x % G;
    if (node >= NN) return;
    int beg = g_off[node], end = g_off[node + 1];
    const uint4* Hv = reinterpret_cast<const uint4*>(H);
    float acc[8] = {0, 0, 0, 0, 0, 0, 0, 0};
    for (int j = beg; j < end; j++) {
        int s = __ldg(g_csr + j);
        uint4 u = __ldg(Hv + (size_t)s * G + t);
        float2 f0 = __half22float2(*reinterpret_cast<__half2*>(&u.x));
        float2 f1 = __half22float2(*reinterpret_cast<__half2*>(&u.y));
        float2 f2 = __half22float2(*reinterpret_cast<__half2*>(&u.z));
        float2 f3 = __half22float2(*reinterpret_cast<__half2*>(&u.w));
        acc[0] += f0.x; acc[1] += f0.y; acc[2] += f1.x; acc[3] += f1.y;
        acc[4] += f2.x; acc[5] += f2.y; acc[6] += f3.x; acc[7] += f3.y;
    }
    float nd = g_norm[node];
    float* o = AGG + (size_t)node * FEAT + t * 8;
    float4 o0 = {acc[0] * nd, acc[1] * nd, acc[2] * nd, acc[3] * nd};
    float4 o1 = {acc[4] * nd, acc[5] * nd, acc[6] * nd, acc[7] * nd};
    *(float4*)o = o0;
    *(float4*)(o + 4) = o1;
}

// layer3: agg3[n] = sum_{s in N(n)} xp[s] * norm[s]   (fp32, 40 feats)
__global__ void k_gather3() {
    int node = blockIdx.x * 16 + threadIdx.x / 16;
    int t = threadIdx.x % 16;
    if (node >= NN || t >= 10) return;
    int beg = g_off[node], end = g_off[node + 1];
    float4 acc = {0, 0, 0, 0};
    for (int j = beg; j < end; j++) {
        int s = __ldg(g_csr + j);
        float ns = g_norm[s];
        float4 v = __ldg((const float4*)g_xp + (size_t)s * 10 + t);
        acc.x = fmaf(v.x, ns, acc.x);
        acc.y = fmaf(v.y, ns, acc.y);
        acc.z = fmaf(v.z, ns, acc.z);
        acc.w = fmaf(v.w, ns, acc.w);
    }
    ((float4*)g_agg3)[(size_t)node * 10 + t] = acc;
}

// ---------------- GEMM: C[M,N] = transform(A[M,K]) @ W[K,N] (+ bias) ---------
// MODE 0: plain A, bias added.   MODE 1: A <- relu(A*csc[k]+csh[k]), no bias.
// 128x64 block tile, 256 threads, 8x4 per thread, double-buffered, f32x2 math.
template <int MODE>
__global__ void __launch_bounds__(256) k_gemm(
    const float* __restrict__ A, const float* __restrict__ W,
    const float* __restrict__ bias, float* __restrict__ C,
    const float* __restrict__ csc, const float* __restrict__ csh,
    int M, int N, int K) {
    __shared__ float As[2][128][17];
    __shared__ __align__(16) float Bs[2][16][64];
    int tid = threadIdx.x;
    int tx = tid & 15, ty = tid >> 4;
    int m0 = blockIdx.x * 128, n0 = blockIdx.y * 64;
    int nt = K / 16;

    unsigned long long acc[8][2];
    #pragma unroll
    for (int i = 0; i < 8; i++) { acc[i][0] = 0ull; acc[i][1] = 0ull; }

    float4 ar[2], br;

    // ---- prologue: load tile 0 ----
    #pragma unroll
    for (int i = 0; i < 2; i++) {
        int f = tid + i * 256, m = f >> 2, q = f & 3;
        int gm = m0 + m;
        float4 v = {0.f, 0.f, 0.f, 0.f};
        if (gm < M) v = *(const float4*)(A + (size_t)gm * K + q * 4);
        if (MODE == 1) {
            float4 sc = *(const float4*)(csc + q * 4);
            float4 sh = *(const float4*)(csh + q * 4);
            v.x = fmaxf(fmaf(v.x, sc.x, sh.x), 0.f);
            v.y = fmaxf(fmaf(v.y, sc.y, sh.y), 0.f);
            v.z = fmaxf(fmaf(v.z, sc.z, sh.z), 0.f);
            v.w = fmaxf(fmaf(v.w, sc.w, sh.w), 0.f);
        }
        ar[i] = v;
    }
    {
        int kk = tid >> 4, n4 = tid & 15;
        if (MODE == 0) {
            br = *(const float4*)(W + (size_t)kk * N + n0 + n4 * 4);
        } else {
            int nb = n0 + n4 * 4;
            br.x = (nb + 0 < N) ? W[(size_t)kk * N + nb + 0] : 0.f;
            br.y = (nb + 1 < N) ? W[(size_t)kk * N + nb + 1] : 0.f;
            br.z = (nb + 2 < N) ? W[(size_t)kk * N + nb + 2] : 0.f;
            br.w = (nb + 3 < N) ? W[(size_t)kk * N + nb + 3] : 0.f;
        }
    }
    #pragma unroll
    for (int i = 0; i < 2; i++) {
        int f = tid + i * 256, m = f >> 2, q = f & 3;
        As[0][m][q * 4 + 0] = ar[i].x;
        As[0][m][q * 4 + 1] = ar[i].y;
        As[0][m][q * 4 + 2] = ar[i].z;
        As[0][m][q * 4 + 3] = ar[i].w;
    }
    {
        int kk = tid >> 4, n4 = tid & 15;
        *(float4*)&Bs[0][kk][n4 * 4] = br;
    }

    // ---- main loop ----
    for (int t = 0; t < nt; t++) {
        __syncthreads();
        if (t + 1 < nt) {
            int k0 = (t + 1) * 16;
            #pragma unroll
            for (int i = 0; i < 2; i++) {
                int f = tid + i * 256, m = f >> 2, q = f & 3;
                int gm = m0 + m;
                float4 v = {0.f, 0.f, 0.f, 0.f};
                if (gm < M) v = *(const float4*)(A + (size_t)gm * K + k0 + q * 4);
                if (MODE == 1) {
                    float4 sc = *(const float4*)(csc + k0 + q * 4);
                    float4 sh = *(const float4*)(csh + k0 + q * 4);
                    v.x = fmaxf(fmaf(v.x, sc.x, sh.x), 0.f);
                    v.y = fmaxf(fmaf(v.y, sc.y, sh.y), 0.f);
                    v.z = fmaxf(fmaf(v.z, sc.z, sh.z), 0.f);
                    v.w = fmaxf(fmaf(v.w, sc.w, sh.w), 0.f);
                }
                ar[i] = v;
            }
            int kk = tid >> 4, n4 = tid & 15;
            if (MODE == 0) {
                br = *(const float4*)(W + (size_t)(k0 + kk) * N + n0 + n4 * 4);
            } else {
                int nb = n0 + n4 * 4;
                br.x = (nb + 0 < N) ? W[(size_t)(k0 + kk) * N + nb + 0] : 0.f;
                br.y = (nb + 1 < N) ? W[(size_t)(k0 + kk) * N + nb + 1] : 0.f;
                br.z = (nb + 2 < N) ? W[(size_t)(k0 + kk) * N + nb + 2] : 0.f;
                br.w = (nb + 3 < N) ? W[(size_t)(k0 + kk) * N + nb + 3] : 0.f;
            }
        }
        int b = t & 1;
        #pragma unroll
        for (int k = 0; k < 16; k++) {
            unsigned long long a2[8];
            #pragma unroll
            for (int i = 0; i < 4; i++) {
                float alo = As[b][ty * 4 + i][k];
                float ahi = As[b][64 + ty * 4 + i][k];
                a2[i] = pk2(alo, alo);
                a2[4 + i] = pk2(ahi, ahi);
            }
            float4 bv = *(float4*)&Bs[b][k][tx * 4];
            unsigned long long b0 = pk2(bv.x, bv.y);
            unsigned long long b1 = pk2(bv.z, bv.w);
            #pragma unroll
            for (int i = 0; i < 8; i++) {
                fma2(acc[i][0], a2[i], b0);
                fma2(acc[i][1], a2[i], b1);
            }
        }
        if (t + 1 < nt) {
            int nb = (t + 1) & 1;
            #pragma unroll
            for (int i = 0; i < 2; i++) {
                int f = tid + i * 256, m = f >> 2, q = f & 3;
                As[nb][m][q * 4 + 0] = ar[i].x;
                As[nb][m][q * 4 + 1] = ar[i].y;
                As[nb][m][q * 4 + 2] = ar[i].z;
                As[nb][m][q * 4 + 3] = ar[i].w;
            }
            int kk = tid >> 4, n4 = tid & 15;
            *(float4*)&Bs[nb][kk][n4 * 4] = br;
        }
    }

    // ---- epilogue ----
    #pragma unroll
    for (int i = 0; i < 8; i++) {
        int m = m0 + ((i < 4) ? (ty * 4 + i) : (64 + ty * 4 + i - 4));
        if (m >= M) continue;
        float2 lo = up2(acc[i][0]);
        float2 hi = up2(acc[i][1]);
        int n = n0 + tx * 4;
        if (MODE == 0) {
            float4 o;
            o.x = lo.x + bias[n + 0];
            o.y = lo.y + bias[n + 1];
            o.z = hi.x + bias[n + 2];
            o.w = hi.y + bias[n + 3];
            *(float4*)(C + (size_t)m * N + n) = o;
        } else {
            if (n + 0 < N) C[(size_t)m * N + n + 0] = lo.x;
            if (n + 1 < N) C[(size_t)m * N + n + 1] = lo.y;
            if (n + 2 < N) C[(size_t)m * N + n + 2] = hi.x;
            if (n + 3 < N) C[(size_t)m * N + n + 3] = hi.y;
        }
    }
}

// ---------------- BN column stats (coalesced, double accumulate) -------------
__global__ void k_colstats(const float* __restrict__ Z, double* __restrict__ sum,
                           double* __restrict__ sq, int M) {
    int col = threadIdx.x;
    int r0 = blockIdx.x * 512;
    int rend = min(r0 + 512, M);
    float s = 0.f, q = 0.f;
    for (int r = r0; r < rend; r++) {
        float v = Z[(size_t)r * 256 + col];
        s += v;
        q = fmaf(v, v, q);
    }
    atomicAdd(&sum[col], (double)s);
    atomicAdd(&sq[col], (double)q);
}

__global__ void k_bnfin(const double* __restrict__ sum, const double* __restrict__ sq,
                        const float* __restrict__ gamma, const float* __restrict__ beta,
                        float* __restrict__ scale, float* __restrict__ shift) {
    int i = threadIdx.x;
    double mean = sum[i] / (double)NN;
    double var = sq[i] / (double)NN - mean * mean;
    float rstd = (float)(1.0 / sqrt(var + (double)EPS));
    float sc = rstd * gamma[i];
    scale[i] = sc;
    shift[i] = beta[i] - (float)mean * sc;
}

// ---------------- final: out = log_softmax(agg3*norm + b3) -------------------
__global__ void k_final(const float* __restrict__ b3, float* __restrict__ out) {
    int gt = blockIdx.x * blockDim.x + threadIdx.x;
    int node = gt >> 5;
    int lane = gt & 31;
    if (node >= NN) return;
    float nrm = g_norm[node];
    float v0 = g_agg3[(size_t)node * 40 + lane] * nrm + __ldg(b3 + lane);
    float v1 = -1e30f;
    if (lane + 32 < 40)
        v1 = g_agg3[(size_t)node * 40 + lane + 32] * nrm + __ldg(b3 + lane + 32);
    float m = fmaxf(v0, v1);
    #pragma unroll
    for (int o = 16; o; o >>= 1) m = fmaxf(m, __shfl_xor_sync(0xffffffffu, m, o));
    float s = expf(v0 - m) + ((lane + 32 < 40) ? expf(v1 - m) : 0.f);
    #pragma unroll
    for (int o = 16; o; o >>= 1) s += __shfl_xor_sync(0xffffffffu, s, o);
    float ls = logf(s);
    out[(size_t)node * 40 + lane] = v0 - m - ls;
    if (lane + 32 < 40)
        out[(size_t)node * 40 + lane + 32] = v1 - m - ls;
}

// ---------------- launch -----------------------------------------------------
extern "C" void kernel_launch(void* const* d_in, const int* in_sizes, int n_in,
                              void* d_out, int out_size) {
    const float* x      = (const float*)d_in[0];
    const int*   src    = (const int*)  d_in[1];
    const int*   dst    = (const int*)  d_in[2];
    const float* W1     = (const float*)d_in[3];
    const float* b1     = (const float*)d_in[4];
    const float* gamma1 = (const float*)d_in[5];
    const float* beta1  = (const float*)d_in[6];
    const float* W2     = (const float*)d_in[7];
    const float* b2     = (const float*)d_in[8];
    const float* gamma2 = (const float*)d_in[9];
    const float* beta2  = (const float*)d_in[10];
    const float* W3     = (const float*)d_in[11];
    const float* b3     = (const float*)d_in[12];
    float* out = (float*)d_out;
    int E = in_sizes[1];

    void *p_deg, *p_stats, *p_bnp, *p_h0, *p_h1;
    void *p_agg1, *p_z1, *p_agg2, *p_z2, *p_xp;
    cudaGetSymbolAddress(&p_deg,   g_deg);
    cudaGetSymbolAddress(&p_stats, g_stats);
    cudaGetSymbolAddress(&p_bnp,   g_bnp);
    cudaGetSymbolAddress(&p_h0,    g_h0);
    cudaGetSymbolAddress(&p_h1,    g_h1);
    cudaGetSymbolAddress(&p_agg1,  g_agg1);
    cudaGetSymbolAddress(&p_z1,    g_z1);
    cudaGetSymbolAddress(&p_agg2,  g_agg2);
    cudaGetSymbolAddress(&p_z2,    g_z2);
    cudaGetSymbolAddress(&p_xp,    g_xp);

    cudaMemsetAsync(p_deg, 0, NN * sizeof(int), 0);
    cudaMemsetAsync(p_stats, 0, 4 * 256 * sizeof(double), 0);

    const int T = 256;
    double* st = (double*)p_stats;
    float* bnp = (float*)p_bnp;

    // CSR build + norms
    k_hist<<<(E + T - 1) / T, T>>>(dst, E);
    k_scan<<<1, 1024>>>();
    k_fill<<<(E + T - 1) / T, T>>>(src, dst, E);
    k_norm_fin<<<(NN + T - 1) / T, T>>>();

    // layer 1
    k_prep0<<<(NN * 64 + T - 1) / T, T>>>(x);
    k_gather_h<128><<<(NN + 15) / 16, T>>>((const __half*)p_h0, (float*)p_agg1);
    k_gemm<0><<<dim3((NN + 127) / 128, 4), T>>>((const float*)p_agg1, W1, b1,
                                                (float*)p_z1, nullptr, nullptr,
                                                NN, 256, 128);
    k_colstats<<<(NN + 511) / 512, 256>>>((const float*)p_z1, st, st + 256, NN);
    k_bnfin<<<1, 256>>>(st, st + 256, gamma1, beta1, bnp, bnp + 256);

    // layer 2
    k_prep1<<<(NN * 128 + T - 1) / T, T>>>();
    k_gather_h<256><<<(NN + 7) / 8, T>>>((const __half*)p_h1, (float*)p_agg2);
    k_gemm<0><<<dim3((NN + 127) / 128, 4), T>>>((const float*)p_agg2, W2, b2,
                                                (float*)p_z2, nullptr, nullptr,
                                                NN, 256, 256);
    k_colstats<<<(NN + 511) / 512, 256>>>((const float*)p_z2, st + 512, st + 768, NN);
    k_bnfin<<<1, 256>>>(st + 512, st + 768, gamma2, beta2, bnp + 512, bnp + 768);

    // layer 3: project-first, then gather, then log_softmax
    k_gemm<1><<<dim3((NN + 127) / 128, 1), T>>>((const float*)p_z2, W3, nullptr,
                                                (float*)p_xp, bnp + 512, bnp + 768,
                                                NN, 40, 256);
    k_gather3<<<(NN + 15) / 16, T>>>();
    k_final<<<((long long)NN * 32 + T - 1) / T, T>>>(b3, out);
}

// round 6
// speedup vs baseline: 3.3013x; 1.5581x over previous
#include <cuda_runtime.h>
#include <cuda_fp16.h>
#include <math.h>
#include <stdint.h>

#define NN 100000
#define EPS 1e-5f

// ---------------- scratch (static device globals) ----------------------------
__device__ int    g_deg[NN];
__device__ int    g_off[NN + 1];
__device__ int    g_cur[NN];
__device__ int    g_csr[3200000];
__device__ float  g_norm[NN];
__device__ __align__(128) __half g_h0[NN * 128];    // x*norm, half
__device__ __align__(128) __half g_agg1[NN * 128];  // gathered, *norm_dst
__device__ __align__(128) __half g_z1[NN * 256];
__device__ __align__(128) __half g_h1[NN * 256];    // relu(bn(z1))*norm
__device__ __align__(128) __half g_agg2[NN * 256];
__device__ __align__(128) __half g_z2[NN * 256];
__device__ __align__(128) __half g_h2[NN * 256];    // relu(bn(z2))*norm
__device__ __align__(128) __half g_xp[NN * 40];     // h2 @ W3 (src-scaled)
__device__ __align__(128) float  g_agg3[NN * 40];
__device__ double g_stats[4 * 256];
__device__ float  g_bnp[4 * 256];
__device__ __align__(128) __half g_w1[256 * 128];   // W1^T [N=256][K=128]
__device__ __align__(128) __half g_w2[256 * 256];   // W2^T
__device__ __align__(128) __half g_w3[40 * 256];    // W3^T [N=40][K=256]

// ---------------- smem addr / ldmatrix / mma helpers --------------------------
__device__ __forceinline__ uint32_t smem_u32(const void* p) {
    uint32_t a;
    asm("{ .reg .u64 t; cvta.to.shared.u64 t, %1; cvt.u32.u64 %0, t; }"
        : "=r"(a) : "l"(p));
    return a;
}

__device__ __forceinline__ void ldsm4(uint32_t* r, uint32_t addr) {
    asm volatile("ldmatrix.sync.aligned.m8n8.x4.shared.b16 {%0,%1,%2,%3}, [%4];"
                 : "=r"(r[0]), "=r"(r[1]), "=r"(r[2]), "=r"(r[3]) : "r"(addr));
}

__device__ __forceinline__ void mma16816(float* d, const uint32_t* a,
                                         const uint32_t* b, const float* c) {
    asm volatile(
        "mma.sync.aligned.m16n8k16.row.col.f32.f16.f16.f32 "
        "{%0,%1,%2,%3}, {%4,%5,%6,%7}, {%8,%9}, {%10,%11,%12,%13};"
        : "=f"(d[0]), "=f"(d[1]), "=f"(d[2]), "=f"(d[3])
        : "r"(a[0]), "r"(a[1]), "r"(a[2]), "r"(a[3]),
          "r"(b[0]), "r"(b[1]),
          "f"(c[0]), "f"(c[1]), "f"(c[2]), "f"(c[3]));
}

// ---------------- CSR build ---------------------------------------------------
__global__ void k_hist(const int* __restrict__ dst, int E) {
    int i = blockIdx.x * blockDim.x + threadIdx.x;
    if (i < E) atomicAdd(&g_deg[__ldg(dst + i)], 1);
}

__global__ void k_scan() {
    __shared__ int sh[1024];
    int tid = threadIdx.x;
    const int C = (NN + 1023) / 1024;
    int base = tid * C;
    int s = 0;
    for (int i = 0; i < C; i++) {
        int idx = base + i;
        if (idx < NN) s += g_deg[idx];
    }
    sh[tid] = s;
    __syncthreads();
    for (int o = 1; o < 1024; o <<= 1) {
        int v = (tid >= o) ? sh[tid - o] : 0;
        __syncthreads();
        sh[tid] += v;
        __syncthreads();
    }
    int run = tid ? sh[tid - 1] : 0;
    for (int i = 0; i < C; i++) {
        int idx = base + i;
        if (idx < NN) {
            g_off[idx] = run;
            g_cur[idx] = run;
            run += g_deg[idx];
        }
    }
    if (tid == 1023) g_off[NN] = sh[1023];
}

__global__ void k_fill(const int* __restrict__ src, const int* __restrict__ dst, int E) {
    int i = blockIdx.x * blockDim.x + threadIdx.x;
    if (i < E) {
        int d = __ldg(dst + i);
        int p = atomicAdd(&g_cur[d], 1);
        g_csr[p] = __ldg(src + i);
    }
}

__global__ void k_norm_fin() {
    int i = blockIdx.x * blockDim.x + threadIdx.x;
    if (i < NN) g_norm[i] = rsqrtf(fmaxf((float)g_deg[i], 1.0f));
}

// ---------------- W transpose+convert: Wh[n*K+k] = half(W[k*N+n]) ------------
__global__ void k_wconv(const float* __restrict__ W, __half* __restrict__ Wh,
                        int K, int N) {
    int i = blockIdx.x * blockDim.x + threadIdx.x;
    if (i >= N * K) return;
    int n = i / K, k = i - n * K;
    Wh[i] = __float2half(W[(size_t)k * N + n]);
}

// ---------------- feature prep ------------------------------------------------
__global__ void k_prep0(const float* __restrict__ x) {
    int t = blockIdx.x * blockDim.x + threadIdx.x;
    if (t >= NN * 64) return;
    int row = t >> 6;
    float n = g_norm[row];
    float2 v = __ldg((const float2*)x + t);
    ((__half2*)g_h0)[t] = __floats2half2_rn(v.x * n, v.y * n);
}

// z(half) -> h(half) = relu(z*sc+sh)*norm
__global__ void k_prep(const __half* __restrict__ Zl, const float* __restrict__ sc,
                       const float* __restrict__ sh, __half* __restrict__ Hh) {
    int t = blockIdx.x * blockDim.x + threadIdx.x;
    if (t >= NN * 128) return;
    int row = t >> 7, c2 = t & 127;
    float n = g_norm[row];
    float2 zf = __half22float2(((const __half2*)Zl)[t]);
    float2 s2 = ((const float2*)sc)[c2];
    float2 h2 = ((const float2*)sh)[c2];
    float a = fmaxf(fmaf(zf.x, s2.x, h2.x), 0.f) * n;
    float b = fmaxf(fmaf(zf.y, s2.y, h2.y), 0.f) * n;
    ((__half2*)Hh)[t] = __floats2half2_rn(a, b);
}

// ---------------- CSR gathers (half in -> half out, unroll 4) -----------------
__device__ __forceinline__ void add8(float* a, uint4 u) {
    __half2* h = (__half2*)&u;
    #pragma unroll
    for (int i = 0; i < 4; i++) {
        float2 f = __half22float2(h[i]);
        a[2 * i] += f.x;
        a[2 * i + 1] += f.y;
    }
}

template <int FEAT>
__global__ void k_gather(const __half* __restrict__ H, __half* __restrict__ OUT) {
    const int G = FEAT / 8;  // threads per node, 16B each
    int node = blockIdx.x * (256 / G) + threadIdx.x / G;
    int t = threadIdx.x % G;
    if (node >= NN) return;
    int beg = g_off[node], end = g_off[node + 1];
    const uint4* Hv = reinterpret_cast<const uint4*>(H);
    float acc[8] = {0, 0, 0, 0, 0, 0, 0, 0};
    int j = beg;
    for (; j + 4 <= end; j += 4) {
        int s0 = __ldg(g_csr + j), s1 = __ldg(g_csr + j + 1);
        int s2 = __ldg(g_csr + j + 2), s3 = __ldg(g_csr + j + 3);
        uint4 u0 = __ldg(Hv + (size_t)s0 * G + t);
        uint4 u1 = __ldg(Hv + (size_t)s1 * G + t);
        uint4 u2 = __ldg(Hv + (size_t)s2 * G + t);
        uint4 u3 = __ldg(Hv + (size_t)s3 * G + t);
        add8(acc, u0); add8(acc, u1); add8(acc, u2); add8(acc, u3);
    }
    for (; j < end; j++) {
        int s = __ldg(g_csr + j);
        add8(acc, __ldg(Hv + (size_t)s * G + t));
    }
    float nd = g_norm[node];
    __half2 o[4];
    #pragma unroll
    for (int i = 0; i < 4; i++)
        o[i] = __floats2half2_rn(acc[2 * i] * nd, acc[2 * i + 1] * nd);
    reinterpret_cast<uint4*>(OUT)[(size_t)node * G + t] = *(uint4*)o;
}

// layer3: agg3[n] = sum_{s in N(n)} xp[s]   (xp half, already src-scaled)
__global__ void k_gather3() {
    int node = blockIdx.x * 32 + threadIdx.x / 8;
    int t = threadIdx.x & 7;
    if (node >= NN || t >= 5) return;
    int beg = g_off[node], end = g_off[node + 1];
    const uint4* Hv = reinterpret_cast<const uint4*>(g_xp);  // 5 uint4 per row
    float acc[8] = {0, 0, 0, 0, 0, 0, 0, 0};
    int j = beg;
    for (; j + 4 <= end; j += 4) {
        int s0 = __ldg(g_csr + j), s1 = __ldg(g_csr + j + 1);
        int s2 = __ldg(g_csr + j + 2), s3 = __ldg(g_csr + j + 3);
        uint4 u0 = __ldg(Hv + (size_t)s0 * 5 + t);
        uint4 u1 = __ldg(Hv + (size_t)s1 * 5 + t);
        uint4 u2 = __ldg(Hv + (size_t)s2 * 5 + t);
        uint4 u3 = __ldg(Hv + (size_t)s3 * 5 + t);
        add8(acc, u0); add8(acc, u1); add8(acc, u2); add8(acc, u3);
    }
    for (; j < end; j++) {
        int s = __ldg(g_csr + j);
        add8(acc, __ldg(Hv + (size_t)s * 5 + t));
    }
    float4* o = (float4*)(g_agg3 + (size_t)node * 40 + t * 8);
    o[0] = make_float4(acc[0], acc[1], acc[2], acc[3]);
    o[1] = make_float4(acc[4], acc[5], acc[6], acc[7]);
}

// ---------------- HMMA GEMM: Z[M,N_] = half(A[M,K_] @ Bt[N_,K_]^T + bias) ----
// CTA 128x64, 8 warps (4M x 2N), warp 32x32, mma.sync m16n8k16 f16->f32.
template <int N_, int K_, bool HAS_BIAS>
__global__ void __launch_bounds__(256) k_gemm_mma(
    const __half* __restrict__ A, const float* __restrict__ bias,
    const __half* __restrict__ Bh, __half* __restrict__ Z, int M) {
    constexpr int KA = K_ + 8;  // halfs per smem row (16B pad, conflict-free ldsm)
    extern __shared__ __half sm[];
    __half* Asm = sm;                 // [128][KA]
    __half* Bsm = sm + 128 * KA;      // [64][KA]

    int tid = threadIdx.x;
    int wid = tid >> 5, lane = tid & 31;
    int m0 = blockIdx.x * 128, n0 = blockIdx.y * 64;

    // load A tile (zeros past M)
    const uint4* Ag = (const uint4*)A;
    for (int i = tid; i < 128 * (K_ / 8); i += 256) {
        int r = i / (K_ / 8), u = i % (K_ / 8);
        uint4 v = make_uint4(0, 0, 0, 0);
        if (m0 + r < M) v = __ldg(Ag + (size_t)(m0 + r) * (K_ / 8) + u);
        *(uint4*)(Asm + r * KA + u * 8) = v;
    }
    // load B tile (zeros past N_)
    const uint4* Bg = (const uint4*)Bh;
    for (int i = tid; i < 64 * (K_ / 8); i += 256) {
        int r = i / (K_ / 8), u = i % (K_ / 8);
        uint4 v = make_uint4(0, 0, 0, 0);
        if (n0 + r < N_) v = __ldg(Bg + (size_t)(n0 + r) * (K_ / 8) + u);
        *(uint4*)(Bsm + r * KA + u * 8) = v;
    }
    __syncthreads();

    int wm = wid & 3, wn = wid >> 2;
    uint32_t a_base = smem_u32(Asm);
    uint32_t b_base = smem_u32(Bsm);

    float acc[2][4][4] = {};

    // A x4 lane map: lanes 0-15 rows 0..15 @k0, lanes 16-31 rows 0..15 @k0+8
    int arow = wm * 32 + (lane & 15);
    int acol = (lane >> 4) * 8;
    // B x4 lane map: g0 rows 0-7 @k0, g1 rows 0-7 @k8, g2 rows 8-15 @k0, g3 @k8
    int brow = wn * 32 + ((lane >> 4) ? 8 : 0) + (lane & 7);
    int bk = ((lane >> 3) & 1) * 8;

    #pragma unroll 4
    for (int k0 = 0; k0 < K_; k0 += 16) {
        uint32_t a[2][4];
        #pragma unroll
        for (int mi = 0; mi < 2; mi++)
            ldsm4(a[mi], a_base + (uint32_t)(((arow + mi * 16) * KA + k0 + acol) * 2));
        uint32_t b[2][4];
        #pragma unroll
        for (int nq = 0; nq < 2; nq++)
            ldsm4(b[nq], b_base + (uint32_t)(((brow + nq * 16) * KA + k0 + bk) * 2));
        #pragma unroll
        for (int mi = 0; mi < 2; mi++)
            #pragma unroll
            for (int ni = 0; ni < 4; ni++)
                mma16816(acc[mi][ni], a[mi], &b[ni >> 1][(ni & 1) * 2], acc[mi][ni]);
    }

    // epilogue: thread t -> rows (t/4, t/4+8), cols (t%4)*2 per 8-col group
    int cbase = n0 + wn * 32 + (lane & 3) * 2;
    #pragma unroll
    for (int mi = 0; mi < 2; mi++) {
        int rowt = m0 + wm * 32 + mi * 16 + (lane >> 2);
        #pragma unroll
        for (int hrow = 0; hrow < 2; hrow++) {
            int rr = rowt + hrow * 8;
            if (rr >= M) continue;
            #pragma unroll
            for (int ni = 0; ni < 4; ni++) {
                int col = cbase + ni * 8;
                if ((N_ % 64 == 0) || (col + 1 < N_)) {
                    float v0 = acc[mi][ni][hrow * 2 + 0];
                    float v1 = acc[mi][ni][hrow * 2 + 1];
                    if (HAS_BIAS) {
                        v0 += __ldg(bias + col);
                        v1 += __ldg(bias + col + 1);
                    }
                    *(__half2*)(Z + (size_t)rr * N_ + col) = __floats2half2_rn(v0, v1);
                }
            }
        }
    }
}

// ---------------- BN column stats (half input, double accumulate) ------------
__global__ void k_colstats(const __half* __restrict__ Zl, double* __restrict__ sum,
                           double* __restrict__ sq, int M) {
    int col = threadIdx.x;
    int r0 = blockIdx.x * 512;
    int rend = min(r0 + 512, M);
    float s = 0.f, q = 0.f;
    for (int r = r0; r < rend; r++) {
        float v = __half2float(Zl[(size_t)r * 256 + col]);
        s += v;
        q = fmaf(v, v, q);
    }
    atomicAdd(&sum[col], (double)s);
    atomicAdd(&sq[col], (double)q);
}

__global__ void k_bnfin(const double* __restrict__ sum, const double* __restrict__ sq,
                        const float* __restrict__ gamma, const float* __restrict__ beta,
                        float* __restrict__ scale, float* __restrict__ shift) {
    int i = threadIdx.x;
    double mean = sum[i] / (double)NN;
    double var = sq[i] / (double)NN - mean * mean;
    float rstd = (float)(1.0 / sqrt(var + (double)EPS));
    float sc = rstd * gamma[i];
    scale[i] = sc;
    shift[i] = beta[i] - (float)mean * sc;
}

// ---------------- final: out = log_softmax(agg3*norm + b3) -------------------
__global__ void k_final(const float* __restrict__ b3, float* __restrict__ out) {
    int gt = blockIdx.x * blockDim.x + threadIdx.x;
    int node = gt >> 5;
    int lane = gt & 31;
    if (node >= NN) return;
    float nrm = g_norm[node];
    float v0 = g_agg3[(size_t)node * 40 + lane] * nrm + __ldg(b3 + lane);
    float v1 = -1e30f;
    if (lane + 32 < 40)
        v1 = g_agg3[(size_t)node * 40 + lane + 32] * nrm + __ldg(b3 + lane + 32);
    float m = fmaxf(v0, v1);
    #pragma unroll
    for (int o = 16; o; o >>= 1) m = fmaxf(m, __shfl_xor_sync(0xffffffffu, m, o));
    float s = expf(v0 - m) + ((lane + 32 < 40) ? expf(v1 - m) : 0.f);
    #pragma unroll
    for (int o = 16; o; o >>= 1) s += __shfl_xor_sync(0xffffffffu, s, o);
    float ls = logf(s);
    out[(size_t)node * 40 + lane] = v0 - m - ls;
    if (lane + 32 < 40)
        out[(size_t)node * 40 + lane + 32] = v1 - m - ls;
}

// ---------------- launch -----------------------------------------------------
extern "C" void kernel_launch(void* const* d_in, const int* in_sizes, int n_in,
                              void* d_out, int out_size) {
    const float* x      = (const float*)d_in[0];
    const int*   src    = (const int*)  d_in[1];
    const int*   dst    = (const int*)  d_in[2];
    const float* W1     = (const float*)d_in[3];
    const float* b1     = (const float*)d_in[4];
    const float* gamma1 = (const float*)d_in[5];
    const float* beta1  = (const float*)d_in[6];
    const float* W2     = (const float*)d_in[7];
    const float* b2     = (const float*)d_in[8];
    const float* gamma2 = (const float*)d_in[9];
    const float* beta2  = (const float*)d_in[10];
    const float* W3     = (const float*)d_in[11];
    const float* b3     = (const float*)d_in[12];
    float* out = (float*)d_out;
    int E = in_sizes[1];

    void *p_deg, *p_stats, *p_bnp, *p_h0, *p_h1, *p_h2;
    void *p_agg1, *p_z1, *p_agg2, *p_z2, *p_xp;
    void *p_w1, *p_w2, *p_w3;
    cudaGetSymbolAddress(&p_deg,   g_deg);
    cudaGetSymbolAddress(&p_stats, g_stats);
    cudaGetSymbolAddress(&p_bnp,   g_bnp);
    cudaGetSymbolAddress(&p_h0,    g_h0);
    cudaGetSymbolAddress(&p_h1,    g_h1);
    cudaGetSymbolAddress(&p_h2,    g_h2);
    cudaGetSymbolAddress(&p_agg1,  g_agg1);
    cudaGetSymbolAddress(&p_z1,    g_z1);
    cudaGetSymbolAddress(&p_agg2,  g_agg2);
    cudaGetSymbolAddress(&p_z2,    g_z2);
    cudaGetSymbolAddress(&p_xp,    g_xp);
    cudaGetSymbolAddress(&p_w1,    g_w1);
    cudaGetSymbolAddress(&p_w2,    g_w2);
    cudaGetSymbolAddress(&p_w3,    g_w3);

    // dynamic smem for the MMA GEMMs: (128+64) rows * (K+8) halfs * 2B
    const int SM1 = 192 * (128 + 8) * 2;  // 52224
    const int SM2 = 192 * (256 + 8) * 2;  // 101376
    const int SM3 = SM2;
    cudaFuncSetAttribute(k_gemm_mma<256, 128, true>,
                         cudaFuncAttributeMaxDynamicSharedMemorySize, SM1);
    cudaFuncSetAttribute(k_gemm_mma<256, 256, true>,
                         cudaFuncAttributeMaxDynamicSharedMemorySize, SM2);
    cudaFuncSetAttribute(k_gemm_mma<40, 256, false>,
                         cudaFuncAttributeMaxDynamicSharedMemorySize, SM3);

    cudaMemsetAsync(p_deg, 0, NN * sizeof(int), 0);
    cudaMemsetAsync(p_stats, 0, 4 * 256 * sizeof(double), 0);

    const int T = 256;
    double* st = (double*)p_stats;
    float* bnp = (float*)p_bnp;
    int mg = (NN + 127) / 128;  // 782

    // W conversions (transpose to [N][K] half)
    k_wconv<<<(256 * 128 + T - 1) / T, T>>>(W1, (__half*)p_w1, 128, 256);
    k_wconv<<<(256 * 256 + T - 1) / T, T>>>(W2, (__half*)p_w2, 256, 256);
    k_wconv<<<(40 * 256 + T - 1) / T, T>>>(W3, (__half*)p_w3, 256, 40);

    // CSR build + norms
    k_hist<<<(E + T - 1) / T, T>>>(dst, E);
    k_scan<<<1, 1024>>>();
    k_fill<<<(E + T - 1) / T, T>>>(src, dst, E);
    k_norm_fin<<<(NN + T - 1) / T, T>>>();

    // layer 1
    k_prep0<<<(NN * 64 + T - 1) / T, T>>>(x);
    k_gather<128><<<(NN + 15) / 16, T>>>((const __half*)p_h0, (__half*)p_agg1);
    k_gemm_mma<256, 128, true><<<dim3(mg, 4), T, SM1>>>(
        (const __half*)p_agg1, b1, (const __half*)p_w1, (__half*)p_z1, NN);
    k_colstats<<<(NN + 511) / 512, 256>>>((const __half*)p_z1, st, st + 256, NN);
    k_bnfin<<<1, 256>>>(st, st + 256, gamma1, beta1, bnp, bnp + 256);
    k_prep<<<(NN * 128 + T - 1) / T, T>>>((const __half*)p_z1, bnp, bnp + 256,
                                          (__half*)p_h1);

    // layer 2
    k_gather<256><<<(NN + 7) / 8, T>>>((const __half*)p_h1, (__half*)p_agg2);
    k_gemm_mma<256, 256, true><<<dim3(mg, 4), T, SM2>>>(
        (const __half*)p_agg2, b2, (const __half*)p_w2, (__half*)p_z2, NN);
    k_colstats<<<(NN + 511) / 512, 256>>>((const __half*)p_z2, st + 512, st + 768, NN);
    k_bnfin<<<1, 256>>>(st + 512, st + 768, gamma2, beta2, bnp + 512, bnp + 768);
    k_prep<<<(NN * 128 + T - 1) / T, T>>>((const __half*)p_z2, bnp + 512, bnp + 768,
                                          (__half*)p_h2);

    // layer 3: xp = h2 @ W3 (src-scaled), gather, log_softmax
    k_gemm_mma<40, 256, false><<<dim3(mg, 1), T, SM3>>>(
        (const __half*)p_h2, nullptr, (const __half*)p_w3, (__half*)p_xp, NN);
    k_gather3<<<(NN + 31) / 32, T>>>();
    k_final<<<((long long)NN * 32 + T - 1) / T, T>>>(b3, out);
}

// round 7
// speedup vs baseline: 3.8694x; 1.1721x over previous
#include <cuda_runtime.h>
#include <cuda_fp16.h>
#include <math.h>
#include <stdint.h>

#define NN 100000
#define EPS 1e-5f
#define NBLK 98   // ceil(NN/1024)

// ---------------- scratch (static device globals) ----------------------------
__device__ int    g_deg[NN];
__device__ int    g_off[NN + 1];
__device__ int    g_cur[NN];
__device__ int    g_bsum[NBLK];
__device__ int    g_csr[3200000];
__device__ float  g_norm[NN];
__device__ __align__(128) __half g_h0[NN * 128];    // x*norm, half
__device__ __align__(128) __half g_agg1[NN * 128];  // gathered, *norm_dst
__device__ __align__(128) __half g_z1[NN * 256];
__device__ __align__(128) __half g_h1[NN * 256];    // relu(bn(z1))*norm
__device__ __align__(128) __half g_agg2[NN * 256];
__device__ __align__(128) __half g_z2[NN * 256];
__device__ __align__(128) __half g_h2[NN * 256];    // relu(bn(z2))*norm
__device__ __align__(128) __half g_xp[NN * 40];     // h2 @ W3 (src-scaled)
__device__ double g_stats[4 * 256];
__device__ float  g_bnp[4 * 256];
__device__ __align__(128) __half g_w1[256 * 128];   // W1^T [N=256][K=128]
__device__ __align__(128) __half g_w2[256 * 256];   // W2^T
__device__ __align__(128) __half g_w3[40 * 256];    // W3^T [N=40][K=256]

// ---------------- smem addr / ldmatrix / mma helpers --------------------------
__device__ __forceinline__ uint32_t smem_u32(const void* p) {
    uint32_t a;
    asm("{ .reg .u64 t; cvta.to.shared.u64 t, %1; cvt.u32.u64 %0, t; }"
        : "=r"(a) : "l"(p));
    return a;
}

__device__ __forceinline__ void ldsm4(uint32_t* r, uint32_t addr) {
    asm volatile("ldmatrix.sync.aligned.m8n8.x4.shared.b16 {%0,%1,%2,%3}, [%4];"
                 : "=r"(r[0]), "=r"(r[1]), "=r"(r[2]), "=r"(r[3]) : "r"(addr));
}

__device__ __forceinline__ void mma16816(float* d, const uint32_t* a,
                                         const uint32_t* b, const float* c) {
    asm volatile(
        "mma.sync.aligned.m16n8k16.row.col.f32.f16.f16.f32 "
        "{%0,%1,%2,%3}, {%4,%5,%6,%7}, {%8,%9}, {%10,%11,%12,%13};"
        : "=f"(d[0]), "=f"(d[1]), "=f"(d[2]), "=f"(d[3])
        : "r"(a[0]), "r"(a[1]), "r"(a[2]), "r"(a[3]),
          "r"(b[0]), "r"(b[1]),
          "f"(c[0]), "f"(c[1]), "f"(c[2]), "f"(c[3]));
}

// ---------------- CSR build ---------------------------------------------------
__global__ void k_hist(const int* __restrict__ dst, int E) {
    int i = blockIdx.x * blockDim.x + threadIdx.x;
    int e = i * 2;
    if (e + 1 < E) {
        int2 d = __ldg((const int2*)dst + i);
        atomicAdd(&g_deg[d.x], 1);
        atomicAdd(&g_deg[d.y], 1);
    } else if (e < E) {
        atomicAdd(&g_deg[__ldg(dst + e)], 1);
    }
}

// 3-phase scan: block sums -> scan sums -> local scan + base
__global__ void k_scan_a() {
    __shared__ int sh[32];
    int i = blockIdx.x * 1024 + threadIdx.x;
    int v = (i < NN) ? g_deg[i] : 0;
    #pragma unroll
    for (int o = 16; o; o >>= 1) v += __shfl_xor_sync(0xffffffffu, v, o);
    if ((threadIdx.x & 31) == 0) sh[threadIdx.x >> 5] = v;
    __syncthreads();
    if (threadIdx.x < 32) {
        int u = sh[threadIdx.x];
        #pragma unroll
        for (int o = 16; o; o >>= 1) u += __shfl_xor_sync(0xffffffffu, u, o);
        if (threadIdx.x == 0) g_bsum[blockIdx.x] = u;
    }
}

__global__ void k_scan_b() {
    __shared__ int sh[128];
    int tid = threadIdx.x;
    int v = (tid < NBLK) ? g_bsum[tid] : 0;
    sh[tid] = v;
    __syncthreads();
    for (int o = 1; o < 128; o <<= 1) {
        int u = (tid >= o) ? sh[tid - o] : 0;
        __syncthreads();
        sh[tid] += u;
        __syncthreads();
    }
    if (tid < NBLK) g_bsum[tid] = sh[tid] - v;  // exclusive
    if (tid == NBLK - 1) g_off[NN] = sh[tid];
}

__global__ void k_scan_c() {
    __shared__ int sh[1024];
    int i = blockIdx.x * 1024 + threadIdx.x;
    int v = (i < NN) ? g_deg[i] : 0;
    sh[threadIdx.x] = v;
    __syncthreads();
    for (int o = 1; o < 1024; o <<= 1) {
        int u = (threadIdx.x >= o) ? sh[threadIdx.x - o] : 0;
        __syncthreads();
        sh[threadIdx.x] += u;
        __syncthreads();
    }
    if (i < NN) {
        int ex = sh[threadIdx.x] - v + g_bsum[blockIdx.x];
        g_off[i] = ex;
        g_cur[i] = ex;
        g_norm[i] = rsqrtf(fmaxf((float)v, 1.0f));
    }
}

__global__ void k_fill(const int* __restrict__ src, const int* __restrict__ dst, int E) {
    int i = blockIdx.x * blockDim.x + threadIdx.x;
    int e = i * 2;
    if (e + 1 < E) {
        int2 d = __ldg((const int2*)dst + i);
        int2 s = __ldg((const int2*)src + i);
        g_csr[atomicAdd(&g_cur[d.x], 1)] = s.x;
        g_csr[atomicAdd(&g_cur[d.y], 1)] = s.y;
    } else if (e < E) {
        g_csr[atomicAdd(&g_cur[__ldg(dst + e)], 1)] = __ldg(src + e);
    }
}

// ---------------- W transpose+convert (fused, all 3) --------------------------
__global__ void k_wconv_all(const float* __restrict__ W1, const float* __restrict__ W2,
                            const float* __restrict__ W3) {
    int i = blockIdx.x * 256 + threadIdx.x;
    if (i < 32768) {                       // g_w1[n*128+k] = W1[k*256+n]
        int n = i >> 7, k = i & 127;
        g_w1[i] = __float2half(__ldg(W1 + k * 256 + n));
    } else if (i < 98304) {                // g_w2[n*256+k] = W2[k*256+n]
        int j = i - 32768;
        int n = j >> 8, k = j & 255;
        g_w2[j] = __float2half(__ldg(W2 + k * 256 + n));
    } else if (i < 108544) {               // g_w3[n*256+k] = W3[k*40+n]
        int j = i - 98304;
        int n = j >> 8, k = j & 255;
        g_w3[j] = __float2half(__ldg(W3 + k * 40 + n));
    }
}

// ---------------- feature prep ------------------------------------------------
__global__ void k_prep0(const float* __restrict__ x) {
    int t = blockIdx.x * blockDim.x + threadIdx.x;
    if (t >= NN * 64) return;
    int row = t >> 6;
    float n = g_norm[row];
    float2 v = __ldcs((const float2*)x + t);
    ((__half2*)g_h0)[t] = __floats2half2_rn(v.x * n, v.y * n);
}

// z(half) -> h(half) = relu(z*sc+sh)*norm
__global__ void k_prep(const __half* __restrict__ Zl, const float* __restrict__ sc,
                       const float* __restrict__ sh, __half* __restrict__ Hh) {
    int t = blockIdx.x * blockDim.x + threadIdx.x;
    if (t >= NN * 128) return;
    int row = t >> 7, c2 = t & 127;
    float n = g_norm[row];
    float2 zf = __half22float2(__ldcs((const __half2*)Zl + t));
    float2 s2 = ((const float2*)sc)[c2];
    float2 h2 = ((const float2*)sh)[c2];
    float a = fmaxf(fmaf(zf.x, s2.x, h2.x), 0.f) * n;
    float b = fmaxf(fmaf(zf.y, s2.y, h2.y), 0.f) * n;
    ((__half2*)Hh)[t] = __floats2half2_rn(a, b);
}

// ---------------- CSR gathers (half in -> half out, unroll 8) -----------------
__device__ __forceinline__ void add8(float* a, uint4 u) {
    __half2* h = (__half2*)&u;
    #pragma unroll
    for (int i = 0; i < 4; i++) {
        float2 f = __half22float2(h[i]);
        a[2 * i] += f.x;
        a[2 * i + 1] += f.y;
    }
}

template <int FEAT>
__global__ void k_gather(const __half* __restrict__ H, __half* __restrict__ OUT) {
    const int G = FEAT / 8;  // threads per node, 16B each
    int node = blockIdx.x * (256 / G) + threadIdx.x / G;
    int t = threadIdx.x % G;
    if (node >= NN) return;
    int beg = g_off[node], end = g_off[node + 1];
    const uint4* Hv = reinterpret_cast<const uint4*>(H);
    float acc[8] = {0, 0, 0, 0, 0, 0, 0, 0};
    int j = beg;
    for (; j + 8 <= end; j += 8) {
        int s[8];
        #pragma unroll
        for (int u = 0; u < 8; u++) s[u] = __ldg(g_csr + j + u);
        uint4 v[8];
        #pragma unroll
        for (int u = 0; u < 8; u++) v[u] = __ldg(Hv + (size_t)s[u] * G + t);
        #pragma unroll
        for (int u = 0; u < 8; u++) add8(acc, v[u]);
    }
    for (; j < end; j++) {
        int s = __ldg(g_csr + j);
        add8(acc, __ldg(Hv + (size_t)s * G + t));
    }
    float nd = g_norm[node];
    __half2 o[4];
    #pragma unroll
    for (int i = 0; i < 4; i++)
        o[i] = __floats2half2_rn(acc[2 * i] * nd, acc[2 * i + 1] * nd);
    __stcs(reinterpret_cast<float4*>(OUT) + (size_t)node * G + t, *(float4*)o);
}

// layer3 gather + log_softmax fused. 8 threads/node, t<5 hold 8 feats each.
__global__ void k_gather3_final(const float* __restrict__ b3, float* __restrict__ out) {
    int node = blockIdx.x * 32 + threadIdx.x / 8;
    int t = threadIdx.x & 7;
    int lane = threadIdx.x & 31;
    unsigned mask = 0xffu << (lane & ~7);
    if (node >= NN) return;
    float acc[8] = {0, 0, 0, 0, 0, 0, 0, 0};
    if (t < 5) {
        int beg = g_off[node], end = g_off[node + 1];
        const uint4* Hv = reinterpret_cast<const uint4*>(g_xp);  // 5 uint4/row
        int j = beg;
        for (; j + 8 <= end; j += 8) {
            int s[8];
            #pragma unroll
            for (int u = 0; u < 8; u++) s[u] = __ldg(g_csr + j + u);
            uint4 v[8];
            #pragma unroll
            for (int u = 0; u < 8; u++) v[u] = __ldg(Hv + (size_t)s[u] * 5 + t);
            #pragma unroll
            for (int u = 0; u < 8; u++) add8(acc, v[u]);
        }
        for (; j < end; j++) {
            int s = __ldg(g_csr + j);
            add8(acc, __ldg(Hv + (size_t)s * 5 + t));
        }
    }
    float nrm = g_norm[node];
    float v[8];
    float lm = -1e30f;
    if (t < 5) {
        #pragma unroll
        for (int i = 0; i < 8; i++) {
            v[i] = acc[i] * nrm + __ldg(b3 + t * 8 + i);
            lm = fmaxf(lm, v[i]);
        }
    }
    #pragma unroll
    for (int o = 4; o; o >>= 1) lm = fmaxf(lm, __shfl_xor_sync(mask, lm, o));
    float ls = 0.f;
    if (t < 5) {
        #pragma unroll
        for (int i = 0; i < 8; i++) ls += __expf(v[i] - lm);
    }
    #pragma unroll
    for (int o = 4; o; o >>= 1) ls += __shfl_xor_sync(mask, ls, o);
    float lg = __logf(ls);
    if (t < 5) {
        float4 o0 = {v[0] - lm - lg, v[1] - lm - lg, v[2] - lm - lg, v[3] - lm - lg};
        float4 o1 = {v[4] - lm - lg, v[5] - lm - lg, v[6] - lm - lg, v[7] - lm - lg};
        float* op = out + (size_t)node * 40 + t * 8;
        *(float4*)op = o0;
        *(float4*)(op + 4) = o1;
    }
}

// ---------------- HMMA GEMM: Z[M,N_] = half(A[M,K_] @ Bt[N_,K_]^T + bias) ----
// CTA 128x64, 8 warps (4M x 2N), warp 32x32, mma.sync m16n8k16 f16->f32.
template <int N_, int K_, bool HAS_BIAS>
__global__ void __launch_bounds__(256) k_gemm_mma(
    const __half* __restrict__ A, const float* __restrict__ bias,
    const __half* __restrict__ Bh, __half* __restrict__ Z, int M) {
    constexpr int KA = K_ + 8;  // halfs per smem row (16B pad, conflict-free ldsm)
    extern __shared__ __half sm[];
    __half* Asm = sm;                 // [128][KA]
    __half* Bsm = sm + 128 * KA;      // [64][KA]

    int tid = threadIdx.x;
    int wid = tid >> 5, lane = tid & 31;
    int m0 = blockIdx.x * 128, n0 = blockIdx.y * 64;

    // load A tile (zeros past M)
    const uint4* Ag = (const uint4*)A;
    for (int i = tid; i < 128 * (K_ / 8); i += 256) {
        int r = i / (K_ / 8), u = i % (K_ / 8);
        uint4 v = make_uint4(0, 0, 0, 0);
        if (m0 + r < M) v = __ldg(Ag + (size_t)(m0 + r) * (K_ / 8) + u);
        *(uint4*)(Asm + r * KA + u * 8) = v;
    }
    // load B tile (zeros past N_)
    const uint4* Bg = (const uint4*)Bh;
    for (int i = tid; i < 64 * (K_ / 8); i += 256) {
        int r = i / (K_ / 8), u = i % (K_ / 8);
        uint4 v = make_uint4(0, 0, 0, 0);
        if (n0 + r < N_) v = __ldg(Bg + (size_t)(n0 + r) * (K_ / 8) + u);
        *(uint4*)(Bsm + r * KA + u * 8) = v;
    }
    __syncthreads();

    int wm = wid & 3, wn = wid >> 2;
    uint32_t a_base = smem_u32(Asm);
    uint32_t b_base = smem_u32(Bsm);

    float acc[2][4][4] = {};

    int arow = wm * 32 + (lane & 15);
    int acol = (lane >> 4) * 8;
    int brow = wn * 32 + ((lane >> 4) ? 8 : 0) + (lane & 7);
    int bk = ((lane >> 3) & 1) * 8;

    #pragma unroll 4
    for (int k0 = 0; k0 < K_; k0 += 16) {
        uint32_t a[2][4];
        #pragma unroll
        for (int mi = 0; mi < 2; mi++)
            ldsm4(a[mi], a_base + (uint32_t)(((arow + mi * 16) * KA + k0 + acol) * 2));
        uint32_t b[2][4];
        #pragma unroll
        for (int nq = 0; nq < 2; nq++)
            ldsm4(b[nq], b_base + (uint32_t)(((brow + nq * 16) * KA + k0 + bk) * 2));
        #pragma unroll
        for (int mi = 0; mi < 2; mi++)
            #pragma unroll
            for (int ni = 0; ni < 4; ni++)
                mma16816(acc[mi][ni], a[mi], &b[ni >> 1][(ni & 1) * 2], acc[mi][ni]);
    }

    int cbase = n0 + wn * 32 + (lane & 3) * 2;
    #pragma unroll
    for (int mi = 0; mi < 2; mi++) {
        int rowt = m0 + wm * 32 + mi * 16 + (lane >> 2);
        #pragma unroll
        for (int hrow = 0; hrow < 2; hrow++) {
            int rr = rowt + hrow * 8;
            if (rr >= M) continue;
            #pragma unroll
            for (int ni = 0; ni < 4; ni++) {
                int col = cbase + ni * 8;
                if ((N_ % 64 == 0) || (col + 1 < N_)) {
                    float v0 = acc[mi][ni][hrow * 2 + 0];
                    float v1 = acc[mi][ni][hrow * 2 + 1];
                    if (HAS_BIAS) {
                        v0 += __ldg(bias + col);
                        v1 += __ldg(bias + col + 1);
                    }
                    *(__half2*)(Z + (size_t)rr * N_ + col) = __floats2half2_rn(v0, v1);
                }
            }
        }
    }
}

// ---------------- BN column stats (half input, double accumulate) ------------
__global__ void k_colstats(const __half* __restrict__ Zl, double* __restrict__ sum,
                           double* __restrict__ sq, int M) {
    int col = threadIdx.x;
    int r0 = blockIdx.x * 512;
    int rend = min(r0 + 512, M);
    float s = 0.f, q = 0.f;
    for (int r = r0; r < rend; r++) {
        float v = __half2float(__ldcs(Zl + (size_t)r * 256 + col));
        s += v;
        q = fmaf(v, v, q);
    }
    atomicAdd(&sum[col], (double)s);
    atomicAdd(&sq[col], (double)q);
}

__global__ void k_bnfin(const double* __restrict__ sum, const double* __restrict__ sq,
                        const float* __restrict__ gamma, const float* __restrict__ beta,
                        float* __restrict__ scale, float* __restrict__ shift) {
    int i = threadIdx.x;
    double mean = sum[i] / (double)NN;
    double var = sq[i] / (double)NN - mean * mean;
    float rstd = (float)(1.0 / sqrt(var + (double)EPS));
    float sc = rstd * gamma[i];
    scale[i] = sc;
    shift[i] = beta[i] - (float)mean * sc;
}

// ---------------- launch -----------------------------------------------------
extern "C" void kernel_launch(void* const* d_in, const int* in_sizes, int n_in,
                              void* d_out, int out_size) {
    const float* x      = (const float*)d_in[0];
    const int*   src    = (const int*)  d_in[1];
    const int*   dst    = (const int*)  d_in[2];
    const float* W1     = (const float*)d_in[3];
    const float* b1     = (const float*)d_in[4];
    const float* gamma1 = (const float*)d_in[5];
    const float* beta1  = (const float*)d_in[6];
    const float* W2     = (const float*)d_in[7];
    const float* b2     = (const float*)d_in[8];
    const float* gamma2 = (const float*)d_in[9];
    const float* beta2  = (const float*)d_in[10];
    const float* W3     = (const float*)d_in[11];
    const float* b3     = (const float*)d_in[12];
    float* out = (float*)d_out;
    int E = in_sizes[1];

    void *p_deg, *p_stats, *p_bnp, *p_h0, *p_h1, *p_h2;
    void *p_agg1, *p_z1, *p_agg2, *p_z2, *p_xp;
    void *p_w1, *p_w2, *p_w3;
    cudaGetSymbolAddress(&p_deg,   g_deg);
    cudaGetSymbolAddress(&p_stats, g_stats);
    cudaGetSymbolAddress(&p_bnp,   g_bnp);
    cudaGetSymbolAddress(&p_h0,    g_h0);
    cudaGetSymbolAddress(&p_h1,    g_h1);
    cudaGetSymbolAddress(&p_h2,    g_h2);
    cudaGetSymbolAddress(&p_agg1,  g_agg1);
    cudaGetSymbolAddress(&p_z1,    g_z1);
    cudaGetSymbolAddress(&p_agg2,  g_agg2);
    cudaGetSymbolAddress(&p_z2,    g_z2);
    cudaGetSymbolAddress(&p_xp,    g_xp);
    cudaGetSymbolAddress(&p_w1,    g_w1);
    cudaGetSymbolAddress(&p_w2,    g_w2);
    cudaGetSymbolAddress(&p_w3,    g_w3);

    const int SM1 = 192 * (128 + 8) * 2;  // 52224
    const int SM2 = 192 * (256 + 8) * 2;  // 101376
    const int SM3 = SM2;
    cudaFuncSetAttribute(k_gemm_mma<256, 128, true>,
                         cudaFuncAttributeMaxDynamicSharedMemorySize, SM1);
    cudaFuncSetAttribute(k_gemm_mma<256, 256, true>,
                         cudaFuncAttributeMaxDynamicSharedMemorySize, SM2);
    cudaFuncSetAttribute(k_gemm_mma<40, 256, false>,
                         cudaFuncAttributeMaxDynamicSharedMemorySize, SM3);

    cudaMemsetAsync(p_deg, 0, NN * sizeof(int), 0);
    cudaMemsetAsync(p_stats, 0, 4 * 256 * sizeof(double), 0);

    const int T = 256;
    double* st = (double*)p_stats;
    float* bnp = (float*)p_bnp;
    int mg = (NN + 127) / 128;  // 782

    // W conversions (fused)
    k_wconv_all<<<(108544 + T - 1) / T, T>>>(W1, W2, W3);

    // CSR build + norms (norm fused into scan_c)
    k_hist<<<(E / 2 + T - 1) / T, T>>>(dst, E);
    k_scan_a<<<NBLK, 1024>>>();
    k_scan_b<<<1, 128>>>();
    k_scan_c<<<NBLK, 1024>>>();
    k_fill<<<(E / 2 + T - 1) / T, T>>>(src, dst, E);

    // layer 1
    k_prep0<<<(NN * 64 + T - 1) / T, T>>>(x);
    k_gather<128><<<(NN + 15) / 16, T>>>((const __half*)p_h0, (__half*)p_agg1);
    k_gemm_mma<256, 128, true><<<dim3(mg, 4), T, SM1>>>(
        (const __half*)p_agg1, b1, (const __half*)p_w1, (__half*)p_z1, NN);
    k_colstats<<<(NN + 511) / 512, 256>>>((const __half*)p_z1, st, st + 256, NN);
    k_bnfin<<<1, 256>>>(st, st + 256, gamma1, beta1, bnp, bnp + 256);
    k_prep<<<(NN * 128 + T - 1) / T, T>>>((const __half*)p_z1, bnp, bnp + 256,
                                          (__half*)p_h1);

    // layer 2
    k_gather<256><<<(NN + 7) / 8, T>>>((const __half*)p_h1, (__half*)p_agg2);
    k_gemm_mma<256, 256, true><<<dim3(mg, 4), T, SM2>>>(
        (const __half*)p_agg2, b2, (const __half*)p_w2, (__half*)p_z2, NN);
    k_colstats<<<(NN + 511) / 512, 256>>>((const __half*)p_z2, st + 512, st + 768, NN);
    k_bnfin<<<1, 256>>>(st + 512, st + 768, gamma2, beta2, bnp + 512, bnp + 768);
    k_prep<<<(NN * 128 + T - 1) / T, T>>>((const __half*)p_z2, bnp + 512, bnp + 768,
                                          (__half*)p_h2);

    // layer 3: xp = h2 @ W3 (src-scaled), fused gather+log_softmax
    k_gemm_mma<40, 256, false><<<dim3(mg, 1), T, SM3>>>(
        (const __half*)p_h2, nullptr, (const __half*)p_w3, (__half*)p_xp, NN);
    k_gather3_final<<<(NN + 31) / 32, T>>>(b3, out);
}